// round 3
// baseline (speedup 1.0000x reference)
#include <cuda_runtime.h>
#include <math.h>

#define CB 2
#define CLQ 512
#define CLKV 4096
#define CDIM 512
#define CH 8
#define CE 10
#define CTOPK 5
#define CHEAD 64
#define CTQ (CB*CLQ)      /* 1024 */
#define CTKV (CB*CLKV)    /* 8192 */
#define CK (CE*CDIM)      /* 5120 */
#define CSCALE 0.125f
#define X_ELEMS (CTQ*CDIM)              /* 524288 */
#define ATTN_ELEMS (CB*CH*CLQ*CLKV)     /* 33554432 */

// ---------------- scratch (static device globals; no runtime allocation) ----
__device__ float g_qp[CTQ*CDIM];
__device__ float g_kp[CTKV*CDIM];
__device__ float g_vp[CTKV*CDIM];
__device__ float g_xbuf[CTQ*CDIM];
__device__ float g_gq[CTQ*CE];
__device__ float g_gk[CTKV*CE];
__device__ float g_gv[CTKV*CE];
__device__ float g_go[CTQ*CE];
__device__ float g_attn_fb[ATTN_ELEMS];   // fallback if d_out only holds x

// ---------------- gate: softmax -> top-5 -> renormalize (one warp / token) --
__global__ void gate_kernel(const float* __restrict__ x,
                            const float* __restrict__ gw,   // [512, E]
                            const float* __restrict__ gb,   // [E]
                            float* __restrict__ g, int T)   // [T, E]
{
    int tok  = (blockIdx.x * blockDim.x + threadIdx.x) >> 5;
    int lane = threadIdx.x & 31;
    if (tok >= T) return;
    const float* xr = x + (size_t)tok * CDIM;
    float acc[CE];
#pragma unroll
    for (int e = 0; e < CE; e++) acc[e] = 0.f;
    for (int i = lane; i < CDIM; i += 32) {
        float xv = xr[i];
        const float* gr = gw + (size_t)i * CE;
#pragma unroll
        for (int e = 0; e < CE; e++) acc[e] += xv * gr[e];
    }
#pragma unroll
    for (int e = 0; e < CE; e++) {
#pragma unroll
        for (int o = 16; o > 0; o >>= 1)
            acc[e] += __shfl_xor_sync(0xffffffffu, acc[e], o);
    }
    if (lane == 0) {
        float l[CE];
#pragma unroll
        for (int e = 0; e < CE; e++) l[e] = acc[e] + gb[e];
        bool used[CE];
#pragma unroll
        for (int e = 0; e < CE; e++) used[e] = false;
        int sel[CTOPK];
        float m = -3.4e38f;
        for (int k = 0; k < CTOPK; k++) {          // strict > : first index wins ties (jax)
            int best = 0; float bv = -3.4e38f;
            for (int e = 0; e < CE; e++)
                if (!used[e] && l[e] > bv) { bv = l[e]; best = e; }
            used[best] = true; sel[k] = best;
            if (k == 0) m = bv;
        }
        float ex[CTOPK]; float s = 0.f;
        for (int k = 0; k < CTOPK; k++) { ex[k] = __expf(l[sel[k]] - m); s += ex[k]; }
        float inv = 1.f / s;
        float outv[CE];
#pragma unroll
        for (int e = 0; e < CE; e++) outv[e] = 0.f;
        for (int k = 0; k < CTOPK; k++) outv[sel[k]] = ex[k] * inv;
        float* gr = g + (size_t)tok * CE;
        for (int e = 0; e < CE; e++) gr[e] = outv[e];
    }
}

// --------- fused-gate MoE GEMM: C[M,512] = A'(g*x)[M,5120] @ W[5120,512] + g.b
// 128x128 block tile, BK=8, 256 threads, 8x8 per thread
__global__ void __launch_bounds__(256) moe_gemm(const float* __restrict__ X,    // [M,512]
                                                const float* __restrict__ G,    // [M,E]
                                                const float* __restrict__ W,    // [5120,512]
                                                const float* __restrict__ bias, // [E,512]
                                                float* __restrict__ C)          // [M,512]
{
    __shared__ float As[8][128];
    __shared__ float Bs[8][128];
    int bm = blockIdx.y << 7;
    int bn = blockIdx.x << 7;
    int tid = threadIdx.x;
    int arow = tid >> 1;
    int acol = (tid & 1) << 2;
    int brow = tid >> 5;
    int bcol = (tid & 31) << 2;
    int tm = (tid >> 4) << 3;
    int tn = (tid & 15) << 3;
    float acc[8][8] = {};
    const float* xrow = X + (size_t)(bm + arow) * CDIM;
    const float* grow = G + (size_t)(bm + arow) * CE;

    for (int k0 = 0; k0 < CK; k0 += 8) {
        int e = k0 >> 9;                       // BK=8 slice never crosses an expert
        float gs = grow[e];
        float4 a4 = *(const float4*)&xrow[(k0 & 511) + acol];
        As[acol+0][arow] = a4.x * gs;
        As[acol+1][arow] = a4.y * gs;
        As[acol+2][arow] = a4.z * gs;
        As[acol+3][arow] = a4.w * gs;
        float4 b4 = *(const float4*)&W[(size_t)(k0 + brow)*CDIM + bn + bcol];
        *(float4*)&Bs[brow][bcol] = b4;
        __syncthreads();
#pragma unroll
        for (int kk = 0; kk < 8; kk++) {
            float4 a0 = *(const float4*)&As[kk][tm];
            float4 a1 = *(const float4*)&As[kk][tm+4];
            float4 b0 = *(const float4*)&Bs[kk][tn];
            float4 b1 = *(const float4*)&Bs[kk][tn+4];
            float a[8]  = {a0.x,a0.y,a0.z,a0.w,a1.x,a1.y,a1.z,a1.w};
            float bb[8] = {b0.x,b0.y,b0.z,b0.w,b1.x,b1.y,b1.z,b1.w};
#pragma unroll
            for (int i = 0; i < 8; i++)
#pragma unroll
                for (int j = 0; j < 8; j++) acc[i][j] += a[i]*bb[j];
        }
        __syncthreads();
    }
    // epilogue: + sum_e g[t,e] * b[e,o]
#pragma unroll
    for (int e = 0; e < CE; e++) {
        float bb[8];
#pragma unroll
        for (int j = 0; j < 8; j++) bb[j] = bias[e*CDIM + bn + tn + j];
#pragma unroll
        for (int i = 0; i < 8; i++) {
            float gi = G[(size_t)(bm + tm + i)*CE + e];
#pragma unroll
            for (int j = 0; j < 8; j++) acc[i][j] += gi * bb[j];
        }
    }
#pragma unroll
    for (int i = 0; i < 8; i++) {
        *(float4*)&C[(size_t)(bm+tm+i)*CDIM + bn + tn]     =
            make_float4(acc[i][0],acc[i][1],acc[i][2],acc[i][3]);
        *(float4*)&C[(size_t)(bm+tm+i)*CDIM + bn + tn + 4] =
            make_float4(acc[i][4],acc[i][5],acc[i][6],acc[i][7]);
    }
}

// ---------------- QK^T * scale -> attn logits (64x64 tile per block) --------
__global__ void __launch_bounds__(256) qk_kernel(const float* __restrict__ qp,
                                                 const float* __restrict__ kp,
                                                 float* __restrict__ attn)
{
    __shared__ float Qs[64][65];   // [d][q]
    __shared__ float Ks[64][65];   // [d][k]
    int bh = blockIdx.z;
    int b = bh >> 3, h = bh & 7;
    int q0 = blockIdx.y << 6;
    int k0 = blockIdx.x << 6;
    int tid = threadIdx.x;
#pragma unroll
    for (int l = 0; l < 4; l++) {
        int idx = tid + l*256;
        int r = idx >> 4;
        int d = (idx & 15) << 2;
        float4 qv = *(const float4*)&qp[((size_t)(b*CLQ + q0 + r))*CDIM + h*CHEAD + d];
        Qs[d+0][r]=qv.x; Qs[d+1][r]=qv.y; Qs[d+2][r]=qv.z; Qs[d+3][r]=qv.w;
        float4 kv4 = *(const float4*)&kp[((size_t)(b*CLKV + k0 + r))*CDIM + h*CHEAD + d];
        Ks[d+0][r]=kv4.x; Ks[d+1][r]=kv4.y; Ks[d+2][r]=kv4.z; Ks[d+3][r]=kv4.w;
    }
    __syncthreads();
    int tr = (tid >> 4) << 2;
    int tc = (tid & 15) << 2;
    float acc[4][4] = {};
#pragma unroll
    for (int d = 0; d < 64; d++) {
        float a[4], bb[4];
#pragma unroll
        for (int i = 0; i < 4; i++) a[i]  = Qs[d][tr+i];
#pragma unroll
        for (int j = 0; j < 4; j++) bb[j] = Ks[d][tc+j];
#pragma unroll
        for (int i = 0; i < 4; i++)
#pragma unroll
            for (int j = 0; j < 4; j++) acc[i][j] += a[i]*bb[j];
    }
#pragma unroll
    for (int i = 0; i < 4; i++) {
        *(float4*)&attn[((size_t)(bh*CLQ + q0 + tr + i))*CLKV + k0 + tc] =
            make_float4(acc[i][0]*CSCALE, acc[i][1]*CSCALE,
                        acc[i][2]*CSCALE, acc[i][3]*CSCALE);
    }
}

// ---------------- row softmax over 4096, in place (one block / row) ---------
__global__ void __launch_bounds__(256) softmax_kernel(float* __restrict__ attn)
{
    __shared__ float red[32];
    size_t row = (size_t)blockIdx.x * CLKV;
    int tid = threadIdx.x;
    float v[16];
    float m = -3.4e38f;
#pragma unroll
    for (int l = 0; l < 4; l++) {
        float4 x4 = *(const float4*)&attn[row + tid*4 + l*1024];
        v[l*4+0]=x4.x; v[l*4+1]=x4.y; v[l*4+2]=x4.z; v[l*4+3]=x4.w;
    }
#pragma unroll
    for (int i = 0; i < 16; i++) m = fmaxf(m, v[i]);
#pragma unroll
    for (int o = 16; o > 0; o >>= 1) m = fmaxf(m, __shfl_xor_sync(~0u, m, o));
    if ((tid & 31) == 0) red[tid >> 5] = m;
    __syncthreads();
    if (tid < 32) {
        float t = (tid < 8) ? red[tid] : -3.4e38f;
#pragma unroll
        for (int o = 4; o > 0; o >>= 1) t = fmaxf(t, __shfl_xor_sync(~0u, t, o));
        if (tid == 0) red[0] = t;
    }
    __syncthreads();
    m = red[0];
    float s = 0.f;
#pragma unroll
    for (int i = 0; i < 16; i++) { v[i] = __expf(v[i] - m); s += v[i]; }
#pragma unroll
    for (int o = 16; o > 0; o >>= 1) s += __shfl_xor_sync(~0u, s, o);
    __syncthreads();
    if ((tid & 31) == 0) red[tid >> 5] = s;
    __syncthreads();
    if (tid == 0) {
        float t = 0.f;
        for (int i = 0; i < 8; i++) t += red[i];
        red[0] = 1.f / t;
    }
    __syncthreads();
    float inv = red[0];
#pragma unroll
    for (int l = 0; l < 4; l++) {
        *(float4*)&attn[row + tid*4 + l*1024] =
            make_float4(v[l*4]*inv, v[l*4+1]*inv, v[l*4+2]*inv, v[l*4+3]*inv);
    }
}

// ---------------- P @ V  (64 q-rows x 64 d-cols per block, K-loop 4096) -----
__global__ void __launch_bounds__(256) av_kernel(const float* __restrict__ attn,
                                                 const float* __restrict__ vp,
                                                 float* __restrict__ xbuf)
{
    __shared__ float Ps[64][65];   // [k][q]
    __shared__ float Vs[64][68];   // [k][d]
    int bh = blockIdx.z;
    int b = bh >> 3, h = bh & 7;
    int q0 = blockIdx.y << 6;
    int tid = threadIdx.x;
    int tr = (tid >> 4) << 2;
    int tc = (tid & 15) << 2;
    float acc[4][4] = {};
    for (int k0 = 0; k0 < CLKV; k0 += 64) {
#pragma unroll
        for (int l = 0; l < 4; l++) {
            int idx = tid + l*256;
            int r = idx >> 4;
            int c = (idx & 15) << 2;
            float4 pv = *(const float4*)&attn[((size_t)(bh*CLQ + q0 + r))*CLKV + k0 + c];
            Ps[c+0][r]=pv.x; Ps[c+1][r]=pv.y; Ps[c+2][r]=pv.z; Ps[c+3][r]=pv.w;
            float4 vv = *(const float4*)&vp[((size_t)(b*CLKV + k0 + r))*CDIM + h*CHEAD + c];
            *(float4*)&Vs[r][c] = vv;
        }
        __syncthreads();
#pragma unroll
        for (int kk = 0; kk < 64; kk++) {
            float a[4], bb[4];
#pragma unroll
            for (int i = 0; i < 4; i++) a[i]  = Ps[kk][tr+i];
#pragma unroll
            for (int j = 0; j < 4; j++) bb[j] = Vs[kk][tc+j];
#pragma unroll
            for (int i = 0; i < 4; i++)
#pragma unroll
                for (int j = 0; j < 4; j++) acc[i][j] += a[i]*bb[j];
        }
        __syncthreads();
    }
#pragma unroll
    for (int i = 0; i < 4; i++)
        *(float4*)&xbuf[((size_t)(b*CLQ + q0 + tr + i))*CDIM + h*CHEAD + tc] =
            make_float4(acc[i][0],acc[i][1],acc[i][2],acc[i][3]);
}

// ---------------- launch --------------------------------------------------
extern "C" void kernel_launch(void* const* d_in, const int* in_sizes, int n_in,
                              void* d_out, int out_size)
{
    const float* q    = (const float*)d_in[0];
    const float* kv   = (const float*)d_in[1];
    const float* q_gw = (const float*)d_in[2];
    const float* q_gb = (const float*)d_in[3];
    const float* q_w  = (const float*)d_in[4];
    const float* q_b  = (const float*)d_in[5];
    const float* k_gw = (const float*)d_in[6];
    const float* k_gb = (const float*)d_in[7];
    const float* k_w  = (const float*)d_in[8];
    const float* k_b  = (const float*)d_in[9];
    const float* v_gw = (const float*)d_in[10];
    const float* v_gb = (const float*)d_in[11];
    const float* v_w  = (const float*)d_in[12];
    const float* v_b  = (const float*)d_in[13];
    const float* o_gw = (const float*)d_in[14];
    const float* o_gb = (const float*)d_in[15];
    const float* o_w  = (const float*)d_in[16];
    const float* o_b  = (const float*)d_in[17];
    float* out = (float*)d_out;

    static float *qp=nullptr,*kp=nullptr,*vp=nullptr,*xbuf=nullptr;
    static float *gq=nullptr,*gk=nullptr,*gv=nullptr,*go=nullptr,*afb=nullptr;
    if (!qp) {
        cudaGetSymbolAddress((void**)&qp,   g_qp);
        cudaGetSymbolAddress((void**)&kp,   g_kp);
        cudaGetSymbolAddress((void**)&vp,   g_vp);
        cudaGetSymbolAddress((void**)&xbuf, g_xbuf);
        cudaGetSymbolAddress((void**)&gq,   g_gq);
        cudaGetSymbolAddress((void**)&gk,   g_gk);
        cudaGetSymbolAddress((void**)&gv,   g_gv);
        cudaGetSymbolAddress((void**)&go,   g_go);
        cudaGetSymbolAddress((void**)&afb,  g_attn_fb);
    }
    // output layout: x (524288 floats) then attn (33554432 floats)
    float* attn = (out_size >= (X_ELEMS + ATTN_ELEMS)) ? (out + X_ELEMS) : afb;

    gate_kernel<<<CTQ/8, 256>>>(q,  q_gw, q_gb, gq, CTQ);
    gate_kernel<<<CTKV/8, 256>>>(kv, k_gw, k_gb, gk, CTKV);
    gate_kernel<<<CTKV/8, 256>>>(kv, v_gw, v_gb, gv, CTKV);

    moe_gemm<<<dim3(4, CTQ/128),  256>>>(q,  gq, q_w, q_b, qp);
    moe_gemm<<<dim3(4, CTKV/128), 256>>>(kv, gk, k_w, k_b, kp);
    moe_gemm<<<dim3(4, CTKV/128), 256>>>(kv, gv, v_w, v_b, vp);

    qk_kernel<<<dim3(CLKV/64, CLQ/64, CB*CH), 256>>>(qp, kp, attn);
    softmax_kernel<<<CB*CH*CLQ, 256>>>(attn);
    av_kernel<<<dim3(1, CLQ/64, CB*CH), 256>>>(attn, vp, xbuf);

    gate_kernel<<<CTQ/8, 256>>>(xbuf, o_gw, o_gb, go, CTQ);
    moe_gemm<<<dim3(4, CTQ/128), 256>>>(xbuf, go, o_w, o_b, out);
}

// round 4
// speedup vs baseline: 1.1963x; 1.1963x over previous
#include <cuda_runtime.h>
#include <math.h>
#include <stdint.h>

#define CB 2
#define CLQ 512
#define CLKV 4096
#define CDIM 512
#define CH 8
#define CE 10
#define CTOPK 5
#define CHEAD 64
#define CTQ (CB*CLQ)      /* 1024 */
#define CTKV (CB*CLKV)    /* 8192 */
#define CK (CE*CDIM)      /* 5120 */
#define CSCALE 0.125f
#define X_ELEMS (CTQ*CDIM)              /* 524288 */
#define ATTN_ELEMS (CB*CH*CLQ*CLKV)     /* 33554432 */

// ---------------- scratch (static device globals) ---------------------------
__device__ float g_qp[CTQ*CDIM];
__device__ float g_kp[CTKV*CDIM];
__device__ float g_vp[CTKV*CDIM];
__device__ float g_xbuf[CTQ*CDIM];
__device__ float g_gq[CTQ*CE];
__device__ float g_gk[CTKV*CE];
__device__ float g_gv[CTKV*CE];
__device__ float g_go[CTQ*CE];
__device__ float g_gbq[CTQ*CDIM];
__device__ float g_gbk[CTKV*CDIM];
__device__ float g_gbv[CTKV*CDIM];
__device__ float g_gbo[CTQ*CDIM];
__device__ float g_attn_fb[ATTN_ELEMS];

// ---------------- helpers ---------------------------------------------------
__device__ __forceinline__ uint32_t f2tf32(float x) {
    uint32_t u;
    asm("cvt.rna.tf32.f32 %0, %1;" : "=r"(u) : "f"(x));
    return u;
}

__device__ __forceinline__ void mma_tf32(float c[4],
                                         uint32_t a0, uint32_t a1, uint32_t a2, uint32_t a3,
                                         uint32_t b0, uint32_t b1) {
    asm volatile(
        "mma.sync.aligned.m16n8k8.row.col.f32.tf32.tf32.f32 "
        "{%0,%1,%2,%3}, {%4,%5,%6,%7}, {%8,%9}, {%0,%1,%2,%3};"
        : "+f"(c[0]), "+f"(c[1]), "+f"(c[2]), "+f"(c[3])
        : "r"(a0), "r"(a1), "r"(a2), "r"(a3), "r"(b0), "r"(b1));
}

// ---------------- gate: softmax -> top-5 -> renorm + gbias (warp/token) -----
__global__ void gate_kernel(const float* __restrict__ x,
                            const float* __restrict__ gw,   // [512, E]
                            const float* __restrict__ gb,   // [E]
                            const float* __restrict__ bias, // [E, 512]
                            float* __restrict__ g,          // [T, E]
                            float* __restrict__ gbias,      // [T, 512]
                            int T)
{
    int tok  = (blockIdx.x * blockDim.x + threadIdx.x) >> 5;
    int lane = threadIdx.x & 31;
    if (tok >= T) return;
    const float* xr = x + (size_t)tok * CDIM;
    float acc[CE];
#pragma unroll
    for (int e = 0; e < CE; e++) acc[e] = 0.f;
    for (int i = lane; i < CDIM; i += 32) {
        float xv = xr[i];
        const float* gr = gw + (size_t)i * CE;
#pragma unroll
        for (int e = 0; e < CE; e++) acc[e] += xv * gr[e];
    }
#pragma unroll
    for (int e = 0; e < CE; e++) {
#pragma unroll
        for (int o = 16; o > 0; o >>= 1)
            acc[e] += __shfl_xor_sync(0xffffffffu, acc[e], o);
    }
    float outv[CE];
#pragma unroll
    for (int e = 0; e < CE; e++) outv[e] = 0.f;
    if (lane == 0) {
        float l[CE];
#pragma unroll
        for (int e = 0; e < CE; e++) l[e] = acc[e] + gb[e];
        bool used[CE];
#pragma unroll
        for (int e = 0; e < CE; e++) used[e] = false;
        int sel[CTOPK];
        float m = -3.4e38f;
        for (int k = 0; k < CTOPK; k++) {          // strict >: first index wins ties
            int best = 0; float bv = -3.4e38f;
            for (int e = 0; e < CE; e++)
                if (!used[e] && l[e] > bv) { bv = l[e]; best = e; }
            used[best] = true; sel[k] = best;
            if (k == 0) m = bv;
        }
        float ex[CTOPK]; float s = 0.f;
        for (int k = 0; k < CTOPK; k++) { ex[k] = __expf(l[sel[k]] - m); s += ex[k]; }
        float inv = 1.f / s;
        for (int k = 0; k < CTOPK; k++) outv[sel[k]] = ex[k] * inv;
        float* gr = g + (size_t)tok * CE;
        for (int e = 0; e < CE; e++) gr[e] = outv[e];
    }
    __syncwarp();
    float ge[CE];
#pragma unroll
    for (int e = 0; e < CE; e++) ge[e] = __shfl_sync(0xffffffffu, outv[e], 0);
    float* gbo = gbias + (size_t)tok * CDIM;
#pragma unroll
    for (int c0 = 0; c0 < CDIM; c0 += 32) {
        int c = c0 + lane;
        float s = 0.f;
#pragma unroll
        for (int e = 0; e < CE; e++) s += ge[e] * bias[e*CDIM + c];
        gbo[c] = s;
    }
}

// --------- tf32 tensor-core MoE GEMM ---------------------------------------
// C[M,512] = A'(g*x)[M,5120] @ W[5120,512] + gbias,  A'[t,k]=g[t,k>>9]*x[t,k&511]
// BM x BN CTA tile, BK=16, WR x WC warps, warp tile (BM/WR)x(BN/WC),
// mma.m16n8k8 tf32. SMEM stored in fragment-permuted order -> LDS.128/LDS.64.
template<int BM, int BN, int WR, int WC>
__global__ void __launch_bounds__(WR*WC*32) moe_mma(const float* __restrict__ X,
                                                    const float* __restrict__ G,
                                                    const float* __restrict__ W,
                                                    const float* __restrict__ GB,
                                                    float* __restrict__ C)
{
    constexpr int THREADS = WR * WC * 32;
    constexpr int MT = BM / WR / 16;     // mma m-tiles per warp
    constexpr int NT = BN / WC / 8;      // mma n-tiles per warp
    constexpr int LA = BM * 4 / THREADS; // float4 A loads per thread
    constexpr int LB = BN * 4 / THREADS; // float4 B loads per thread
    static_assert(LA == 2 && LB == 2, "staging assumes 2 loads per thread");

    __shared__ float As[2 * (BM/16) * 32 * 4];   // [k8][m_tile][lane][slot]
    __shared__ float Bs[2 * (BN/8)  * 32 * 2];   // [k8][n_tile][lane][slot]

    const int tid  = threadIdx.x;
    const int w    = tid >> 5;
    const int lane = tid & 31;
    const int wr   = w / WC;
    const int wc   = w % WC;
    const int bm   = blockIdx.y * BM;
    const int bn   = blockIdx.x * BN;

    // --- precompute staging coordinates ---
    int am[LA], ak4[LA], abase[LA];
#pragma unroll
    for (int l = 0; l < LA; l++) {
        int idx = tid + l * THREADS;
        am[l]  = idx >> 2;
        ak4[l] = (idx & 3) << 2;
        int k8 = ak4[l] >> 3;
        int mt = am[l] >> 4;
        abase[l] = ((k8 * (BM/16) + mt) * 32 + ((am[l] & 7) << 2)) * 4
                 + ((am[l] >> 3) & 1) + 2 * ((ak4[l] >> 2) & 1);
    }
    int br[LB], bn4[LB], bbase[LB];
#pragma unroll
    for (int l = 0; l < LB; l++) {
        int idx = tid + l * THREADS;
        br[l]  = idx / (BN/4);
        bn4[l] = (idx % (BN/4)) << 2;
        bbase[l] = (((br[l] >> 3) * (BN/8) + (bn4[l] >> 3)) * 32
                    + ((bn4[l] & 7) << 2) + (br[l] & 3)) * 2 + ((br[l] >> 2) & 1);
    }

    float4 pa[LA], pb[LB];
    float  ga[LA];
    auto load_tiles = [&](int k0) {
#pragma unroll
        for (int l = 0; l < LA; l++) {
            pa[l] = *(const float4*)&X[(size_t)(bm + am[l]) * CDIM + (k0 & 511) + ak4[l]];
            ga[l] = G[(size_t)(bm + am[l]) * CE + (k0 >> 9)];
        }
#pragma unroll
        for (int l = 0; l < LB; l++)
            pb[l] = *(const float4*)&W[(size_t)(k0 + br[l]) * CDIM + bn + bn4[l]];
    };

    float c[MT][NT][4] = {};
    const uint32_t* Asu = (const uint32_t*)As;
    const uint32_t* Bsu = (const uint32_t*)Bs;

    load_tiles(0);
    for (int k0 = 0; k0 < CK; k0 += 16) {
        __syncthreads();
#pragma unroll
        for (int l = 0; l < LA; l++) {
            float g = ga[l];
            As[abase[l] + 0]  = __uint_as_float(f2tf32(pa[l].x * g));
            As[abase[l] + 4]  = __uint_as_float(f2tf32(pa[l].y * g));
            As[abase[l] + 8]  = __uint_as_float(f2tf32(pa[l].z * g));
            As[abase[l] + 12] = __uint_as_float(f2tf32(pa[l].w * g));
        }
#pragma unroll
        for (int l = 0; l < LB; l++) {
            Bs[bbase[l] + 0]  = __uint_as_float(f2tf32(pb[l].x));
            Bs[bbase[l] + 8]  = __uint_as_float(f2tf32(pb[l].y));
            Bs[bbase[l] + 16] = __uint_as_float(f2tf32(pb[l].z));
            Bs[bbase[l] + 24] = __uint_as_float(f2tf32(pb[l].w));
        }
        __syncthreads();
        if (k0 + 16 < CK) load_tiles(k0 + 16);
#pragma unroll
        for (int k8 = 0; k8 < 2; k8++) {
            uint4 a[MT];
            uint2 b[NT];
#pragma unroll
            for (int i = 0; i < MT; i++)
                a[i] = *(const uint4*)&Asu[((k8 * (BM/16) + wr*MT + i) * 32 + lane) * 4];
#pragma unroll
            for (int j = 0; j < NT; j++)
                b[j] = *(const uint2*)&Bsu[((k8 * (BN/8) + wc*NT + j) * 32 + lane) * 2];
#pragma unroll
            for (int i = 0; i < MT; i++)
#pragma unroll
                for (int j = 0; j < NT; j++)
                    mma_tf32(c[i][j], a[i].x, a[i].y, a[i].z, a[i].w, b[j].x, b[j].y);
        }
    }

    // epilogue: + gbias
#pragma unroll
    for (int i = 0; i < MT; i++) {
#pragma unroll
        for (int j = 0; j < NT; j++) {
            int row = bm + wr*MT*16 + i*16 + (lane >> 2);
            int col = bn + wc*NT*8 + j*8 + ((lane & 3) << 1);
            float2 b0 = *(const float2*)&GB[(size_t)row * CDIM + col];
            float2 b1 = *(const float2*)&GB[(size_t)(row + 8) * CDIM + col];
            *(float2*)&C[(size_t)row * CDIM + col] =
                make_float2(c[i][j][0] + b0.x, c[i][j][1] + b0.y);
            *(float2*)&C[(size_t)(row + 8) * CDIM + col] =
                make_float2(c[i][j][2] + b1.x, c[i][j][3] + b1.y);
        }
    }
}

// ---------------- QK^T * scale -> attn logits (64x64 tile per block) --------
__global__ void __launch_bounds__(256) qk_kernel(const float* __restrict__ qp,
                                                 const float* __restrict__ kp,
                                                 float* __restrict__ attn)
{
    __shared__ float Qs[64][65];   // [d][q]
    __shared__ float Ks[64][65];   // [d][k]
    int bh = blockIdx.z;
    int b = bh >> 3, h = bh & 7;
    int q0 = blockIdx.y << 6;
    int k0 = blockIdx.x << 6;
    int tid = threadIdx.x;
#pragma unroll
    for (int l = 0; l < 4; l++) {
        int idx = tid + l*256;
        int r = idx >> 4;
        int d = (idx & 15) << 2;
        float4 qv = *(const float4*)&qp[((size_t)(b*CLQ + q0 + r))*CDIM + h*CHEAD + d];
        Qs[d+0][r]=qv.x; Qs[d+1][r]=qv.y; Qs[d+2][r]=qv.z; Qs[d+3][r]=qv.w;
        float4 kv4 = *(const float4*)&kp[((size_t)(b*CLKV + k0 + r))*CDIM + h*CHEAD + d];
        Ks[d+0][r]=kv4.x; Ks[d+1][r]=kv4.y; Ks[d+2][r]=kv4.z; Ks[d+3][r]=kv4.w;
    }
    __syncthreads();
    int tr = (tid >> 4) << 2;
    int tc = (tid & 15) << 2;
    float acc[4][4] = {};
#pragma unroll
    for (int d = 0; d < 64; d++) {
        float a[4], bb[4];
#pragma unroll
        for (int i = 0; i < 4; i++) a[i]  = Qs[d][tr+i];
#pragma unroll
        for (int j = 0; j < 4; j++) bb[j] = Ks[d][tc+j];
#pragma unroll
        for (int i = 0; i < 4; i++)
#pragma unroll
            for (int j = 0; j < 4; j++) acc[i][j] += a[i]*bb[j];
    }
#pragma unroll
    for (int i = 0; i < 4; i++) {
        *(float4*)&attn[((size_t)(bh*CLQ + q0 + tr + i))*CLKV + k0 + tc] =
            make_float4(acc[i][0]*CSCALE, acc[i][1]*CSCALE,
                        acc[i][2]*CSCALE, acc[i][3]*CSCALE);
    }
}

// ---------------- row softmax over 4096, in place ---------------------------
__global__ void __launch_bounds__(256) softmax_kernel(float* __restrict__ attn)
{
    __shared__ float red[32];
    size_t row = (size_t)blockIdx.x * CLKV;
    int tid = threadIdx.x;
    float v[16];
    float m = -3.4e38f;
#pragma unroll
    for (int l = 0; l < 4; l++) {
        float4 x4 = *(const float4*)&attn[row + tid*4 + l*1024];
        v[l*4+0]=x4.x; v[l*4+1]=x4.y; v[l*4+2]=x4.z; v[l*4+3]=x4.w;
    }
#pragma unroll
    for (int i = 0; i < 16; i++) m = fmaxf(m, v[i]);
#pragma unroll
    for (int o = 16; o > 0; o >>= 1) m = fmaxf(m, __shfl_xor_sync(~0u, m, o));
    if ((tid & 31) == 0) red[tid >> 5] = m;
    __syncthreads();
    if (tid < 32) {
        float t = (tid < 8) ? red[tid] : -3.4e38f;
#pragma unroll
        for (int o = 4; o > 0; o >>= 1) t = fmaxf(t, __shfl_xor_sync(~0u, t, o));
        if (tid == 0) red[0] = t;
    }
    __syncthreads();
    m = red[0];
    float s = 0.f;
#pragma unroll
    for (int i = 0; i < 16; i++) { v[i] = __expf(v[i] - m); s += v[i]; }
#pragma unroll
    for (int o = 16; o > 0; o >>= 1) s += __shfl_xor_sync(~0u, s, o);
    __syncthreads();
    if ((tid & 31) == 0) red[tid >> 5] = s;
    __syncthreads();
    if (tid == 0) {
        float t = 0.f;
        for (int i = 0; i < 8; i++) t += red[i];
        red[0] = 1.f / t;
    }
    __syncthreads();
    float inv = red[0];
#pragma unroll
    for (int l = 0; l < 4; l++) {
        *(float4*)&attn[row + tid*4 + l*1024] =
            make_float4(v[l*4]*inv, v[l*4+1]*inv, v[l*4+2]*inv, v[l*4+3]*inv);
    }
}

// ---------------- P @ V  (64 q-rows x 64 d-cols per block) ------------------
__global__ void __launch_bounds__(256) av_kernel(const float* __restrict__ attn,
                                                 const float* __restrict__ vp,
                                                 float* __restrict__ xbuf)
{
    __shared__ float Ps[64][65];   // [k][q]
    __shared__ float Vs[64][68];   // [k][d]
    int bh = blockIdx.z;
    int b = bh >> 3, h = bh & 7;
    int q0 = blockIdx.y << 6;
    int tid = threadIdx.x;
    int tr = (tid >> 4) << 2;
    int tc = (tid & 15) << 2;
    float acc[4][4] = {};
    for (int k0 = 0; k0 < CLKV; k0 += 64) {
#pragma unroll
        for (int l = 0; l < 4; l++) {
            int idx = tid + l*256;
            int r = idx >> 4;
            int c = (idx & 15) << 2;
            float4 pv = *(const float4*)&attn[((size_t)(bh*CLQ + q0 + r))*CLKV + k0 + c];
            Ps[c+0][r]=pv.x; Ps[c+1][r]=pv.y; Ps[c+2][r]=pv.z; Ps[c+3][r]=pv.w;
            float4 vv = *(const float4*)&vp[((size_t)(b*CLKV + k0 + r))*CDIM + h*CHEAD + c];
            *(float4*)&Vs[r][c] = vv;
        }
        __syncthreads();
#pragma unroll
        for (int kk = 0; kk < 64; kk++) {
            float a[4], bb[4];
#pragma unroll
            for (int i = 0; i < 4; i++) a[i]  = Ps[kk][tr+i];
#pragma unroll
            for (int j = 0; j < 4; j++) bb[j] = Vs[kk][tc+j];
#pragma unroll
            for (int i = 0; i < 4; i++)
#pragma unroll
                for (int j = 0; j < 4; j++) acc[i][j] += a[i]*bb[j];
        }
        __syncthreads();
    }
#pragma unroll
    for (int i = 0; i < 4; i++)
        *(float4*)&xbuf[((size_t)(b*CLQ + q0 + tr + i))*CDIM + h*CHEAD + tc] =
            make_float4(acc[i][0],acc[i][1],acc[i][2],acc[i][3]);
}

// ---------------- launch ----------------------------------------------------
extern "C" void kernel_launch(void* const* d_in, const int* in_sizes, int n_in,
                              void* d_out, int out_size)
{
    const float* q    = (const float*)d_in[0];
    const float* kv   = (const float*)d_in[1];
    const float* q_gw = (const float*)d_in[2];
    const float* q_gb = (const float*)d_in[3];
    const float* q_w  = (const float*)d_in[4];
    const float* q_b  = (const float*)d_in[5];
    const float* k_gw = (const float*)d_in[6];
    const float* k_gb = (const float*)d_in[7];
    const float* k_w  = (const float*)d_in[8];
    const float* k_b  = (const float*)d_in[9];
    const float* v_gw = (const float*)d_in[10];
    const float* v_gb = (const float*)d_in[11];
    const float* v_w  = (const float*)d_in[12];
    const float* v_b  = (const float*)d_in[13];
    const float* o_gw = (const float*)d_in[14];
    const float* o_gb = (const float*)d_in[15];
    const float* o_w  = (const float*)d_in[16];
    const float* o_b  = (const float*)d_in[17];
    float* out = (float*)d_out;

    static float *qp=nullptr,*kp=nullptr,*vp=nullptr,*xbuf=nullptr;
    static float *gq=nullptr,*gk=nullptr,*gv=nullptr,*go=nullptr,*afb=nullptr;
    static float *gbq=nullptr,*gbk=nullptr,*gbv=nullptr,*gbo=nullptr;
    if (!qp) {
        cudaGetSymbolAddress((void**)&qp,   g_qp);
        cudaGetSymbolAddress((void**)&kp,   g_kp);
        cudaGetSymbolAddress((void**)&vp,   g_vp);
        cudaGetSymbolAddress((void**)&xbuf, g_xbuf);
        cudaGetSymbolAddress((void**)&gq,   g_gq);
        cudaGetSymbolAddress((void**)&gk,   g_gk);
        cudaGetSymbolAddress((void**)&gv,   g_gv);
        cudaGetSymbolAddress((void**)&go,   g_go);
        cudaGetSymbolAddress((void**)&afb,  g_attn_fb);
        cudaGetSymbolAddress((void**)&gbq,  g_gbq);
        cudaGetSymbolAddress((void**)&gbk,  g_gbk);
        cudaGetSymbolAddress((void**)&gbv,  g_gbv);
        cudaGetSymbolAddress((void**)&gbo,  g_gbo);
    }
    // output layout: x (524288 floats) then attn (33554432 floats)
    float* attn = (out_size >= (X_ELEMS + ATTN_ELEMS)) ? (out + X_ELEMS) : afb;

    gate_kernel<<<CTQ/8, 256>>>(q,  q_gw, q_gb, q_b, gq, gbq, CTQ);
    gate_kernel<<<CTKV/8, 256>>>(kv, k_gw, k_gb, k_b, gk, gbk, CTKV);
    gate_kernel<<<CTKV/8, 256>>>(kv, v_gw, v_gb, v_b, gv, gbv, CTKV);

    moe_mma<64,64,2,2>  <<<dim3(CDIM/64,  CTQ/64),  128>>>(q,  gq, q_w, gbq, qp);
    moe_mma<128,128,2,4><<<dim3(CDIM/128, CTKV/128),256>>>(kv, gk, k_w, gbk, kp);
    moe_mma<128,128,2,4><<<dim3(CDIM/128, CTKV/128),256>>>(kv, gv, v_w, gbv, vp);

    qk_kernel<<<dim3(CLKV/64, CLQ/64, CB*CH), 256>>>(qp, kp, attn);
    softmax_kernel<<<CB*CH*CLQ, 256>>>(attn);
    av_kernel<<<dim3(1, CLQ/64, CB*CH), 256>>>(attn, vp, xbuf);

    gate_kernel<<<CTQ/8, 256>>>(xbuf, o_gw, o_gb, o_b, go, gbo, CTQ);
    moe_mma<64,64,2,2><<<dim3(CDIM/64, CTQ/64), 128>>>(xbuf, go, o_w, gbo, out);
}

// round 5
// speedup vs baseline: 1.4667x; 1.2261x over previous
#include <cuda_runtime.h>
#include <math.h>
#include <stdint.h>

#define CB 2
#define CLQ 512
#define CLKV 4096
#define CDIM 512
#define CH 8
#define CE 10
#define CTOPK 5
#define CHEAD 64
#define CTQ (CB*CLQ)      /* 1024 */
#define CTKV (CB*CLKV)    /* 8192 */
#define CK (CE*CDIM)      /* 5120 */
#define CSCALE 0.125f
#define X_ELEMS (CTQ*CDIM)              /* 524288 */
#define ATTN_ELEMS (CB*CH*CLQ*CLKV)     /* 33554432 */
#define KSPLIT 4

// ---------------- scratch (static device globals) ---------------------------
__device__ float g_qp[CTQ*CDIM];
__device__ float g_kp[CTKV*CDIM];
__device__ float g_vp[CTKV*CDIM];
__device__ float g_xbuf[CTQ*CDIM];
__device__ float g_gq[CTQ*CE];
__device__ float g_gk[CTKV*CE];
__device__ float g_gv[CTKV*CE];
__device__ float g_go[CTQ*CE];
__device__ float g_gbq[CTQ*CDIM];
__device__ float g_gbk[CTKV*CDIM];
__device__ float g_gbv[CTKV*CDIM];
__device__ float g_gbo[CTQ*CDIM];
__device__ float g_part[KSPLIT*CTQ*CDIM];
__device__ float g_attn_fb[ATTN_ELEMS];

// ---------------- helpers ---------------------------------------------------
__device__ __forceinline__ uint32_t f2tf32(float x) {
    uint32_t u;
    asm("cvt.rna.tf32.f32 %0, %1;" : "=r"(u) : "f"(x));
    return u;
}

__device__ __forceinline__ void mma_tf32(float c[4],
                                         uint32_t a0, uint32_t a1, uint32_t a2, uint32_t a3,
                                         uint32_t b0, uint32_t b1) {
    asm volatile(
        "mma.sync.aligned.m16n8k8.row.col.f32.tf32.tf32.f32 "
        "{%0,%1,%2,%3}, {%4,%5,%6,%7}, {%8,%9}, {%0,%1,%2,%3};"
        : "+f"(c[0]), "+f"(c[1]), "+f"(c[2]), "+f"(c[3])
        : "r"(a0), "r"(a1), "r"(a2), "r"(a3), "r"(b0), "r"(b1));
}

// ---------------- gate: softmax -> top-5 -> renorm + gbias (warp/token) -----
__global__ void gate_kernel(const float* __restrict__ x,
                            const float* __restrict__ gw,   // [512, E]
                            const float* __restrict__ gb,   // [E]
                            const float* __restrict__ bias, // [E, 512]
                            float* __restrict__ g,          // [T, E]
                            float* __restrict__ gbias,      // [T, 512]
                            int T)
{
    int tok  = (blockIdx.x * blockDim.x + threadIdx.x) >> 5;
    int lane = threadIdx.x & 31;
    if (tok >= T) return;
    const float* xr = x + (size_t)tok * CDIM;
    float acc[CE];
#pragma unroll
    for (int e = 0; e < CE; e++) acc[e] = 0.f;
    for (int i = lane; i < CDIM; i += 32) {
        float xv = xr[i];
        const float* gr = gw + (size_t)i * CE;
#pragma unroll
        for (int e = 0; e < CE; e++) acc[e] += xv * gr[e];
    }
#pragma unroll
    for (int e = 0; e < CE; e++) {
#pragma unroll
        for (int o = 16; o > 0; o >>= 1)
            acc[e] += __shfl_xor_sync(0xffffffffu, acc[e], o);
    }
    float outv[CE];
#pragma unroll
    for (int e = 0; e < CE; e++) outv[e] = 0.f;
    if (lane == 0) {
        float l[CE];
#pragma unroll
        for (int e = 0; e < CE; e++) l[e] = acc[e] + gb[e];
        bool used[CE];
#pragma unroll
        for (int e = 0; e < CE; e++) used[e] = false;
        int sel[CTOPK];
        float m = -3.4e38f;
        for (int k = 0; k < CTOPK; k++) {          // strict >: first index wins ties
            int best = 0; float bv = -3.4e38f;
            for (int e = 0; e < CE; e++)
                if (!used[e] && l[e] > bv) { bv = l[e]; best = e; }
            used[best] = true; sel[k] = best;
            if (k == 0) m = bv;
        }
        float ex[CTOPK]; float s = 0.f;
        for (int k = 0; k < CTOPK; k++) { ex[k] = __expf(l[sel[k]] - m); s += ex[k]; }
        float inv = 1.f / s;
        for (int k = 0; k < CTOPK; k++) outv[sel[k]] = ex[k] * inv;
        float* gr = g + (size_t)tok * CE;
        for (int e = 0; e < CE; e++) gr[e] = outv[e];
    }
    __syncwarp();
    float ge[CE];
#pragma unroll
    for (int e = 0; e < CE; e++) ge[e] = __shfl_sync(0xffffffffu, outv[e], 0);
    float* gbo = gbias + (size_t)tok * CDIM;
#pragma unroll
    for (int c0 = 0; c0 < CDIM; c0 += 32) {
        int c = c0 + lane;
        float s = 0.f;
#pragma unroll
        for (int e = 0; e < CE; e++) s += ge[e] * bias[e*CDIM + c];
        gbo[c] = s;
    }
}

// --------- tf32 tensor-core MoE GEMM (split-K capable) ----------------------
// C[M,512] = A'(g*x)[M,5120] @ W[5120,512] (+ gbias if not split)
// blockIdx.z selects K slice [z*klen, (z+1)*klen); partials go to C+z*m_rows*512.
template<int BM, int BN, int WR, int WC>
__global__ void __launch_bounds__(WR*WC*32) moe_mma(const float* __restrict__ X,
                                                    const float* __restrict__ G,
                                                    const float* __restrict__ W,
                                                    const float* __restrict__ GB,
                                                    float* __restrict__ C,
                                                    int klen, int m_rows)
{
    constexpr int THREADS = WR * WC * 32;
    constexpr int MT = BM / WR / 16;
    constexpr int NT = BN / WC / 8;
    constexpr int LA = BM * 4 / THREADS;
    constexpr int LB = BN * 4 / THREADS;
    static_assert(LA == 2 && LB == 2, "staging assumes 2 loads per thread");

    __shared__ float As[2 * (BM/16) * 32 * 4];
    __shared__ float Bs[2 * (BN/8)  * 32 * 2];

    const int tid  = threadIdx.x;
    const int w    = tid >> 5;
    const int lane = tid & 31;
    const int wr   = w / WC;
    const int wc   = w % WC;
    const int bm   = blockIdx.y * BM;
    const int bn   = blockIdx.x * BN;
    const int kbeg = blockIdx.z * klen;
    const int kend = kbeg + klen;

    int am[LA], ak4[LA], abase[LA];
#pragma unroll
    for (int l = 0; l < LA; l++) {
        int idx = tid + l * THREADS;
        am[l]  = idx >> 2;
        ak4[l] = (idx & 3) << 2;
        int k8 = ak4[l] >> 3;
        int mt = am[l] >> 4;
        abase[l] = ((k8 * (BM/16) + mt) * 32 + ((am[l] & 7) << 2)) * 4
                 + ((am[l] >> 3) & 1) + 2 * ((ak4[l] >> 2) & 1);
    }
    int br[LB], bn4[LB], bbase[LB];
#pragma unroll
    for (int l = 0; l < LB; l++) {
        int idx = tid + l * THREADS;
        br[l]  = idx / (BN/4);
        bn4[l] = (idx % (BN/4)) << 2;
        bbase[l] = (((br[l] >> 3) * (BN/8) + (bn4[l] >> 3)) * 32
                    + ((bn4[l] & 7) << 2) + (br[l] & 3)) * 2 + ((br[l] >> 2) & 1);
    }

    float4 pa[LA], pb[LB];
    float  ga[LA];
    auto load_tiles = [&](int k0) {
#pragma unroll
        for (int l = 0; l < LA; l++) {
            pa[l] = *(const float4*)&X[(size_t)(bm + am[l]) * CDIM + (k0 & 511) + ak4[l]];
            ga[l] = G[(size_t)(bm + am[l]) * CE + (k0 >> 9)];
        }
#pragma unroll
        for (int l = 0; l < LB; l++)
            pb[l] = *(const float4*)&W[(size_t)(k0 + br[l]) * CDIM + bn + bn4[l]];
    };

    float c[MT][NT][4] = {};
    const uint32_t* Asu = (const uint32_t*)As;
    const uint32_t* Bsu = (const uint32_t*)Bs;

    load_tiles(kbeg);
    for (int k0 = kbeg; k0 < kend; k0 += 16) {
        __syncthreads();
#pragma unroll
        for (int l = 0; l < LA; l++) {
            float g = ga[l];
            As[abase[l] + 0]  = __uint_as_float(f2tf32(pa[l].x * g));
            As[abase[l] + 4]  = __uint_as_float(f2tf32(pa[l].y * g));
            As[abase[l] + 8]  = __uint_as_float(f2tf32(pa[l].z * g));
            As[abase[l] + 12] = __uint_as_float(f2tf32(pa[l].w * g));
        }
#pragma unroll
        for (int l = 0; l < LB; l++) {
            Bs[bbase[l] + 0]  = __uint_as_float(f2tf32(pb[l].x));
            Bs[bbase[l] + 8]  = __uint_as_float(f2tf32(pb[l].y));
            Bs[bbase[l] + 16] = __uint_as_float(f2tf32(pb[l].z));
            Bs[bbase[l] + 24] = __uint_as_float(f2tf32(pb[l].w));
        }
        __syncthreads();
        if (k0 + 16 < kend) load_tiles(k0 + 16);
#pragma unroll
        for (int k8 = 0; k8 < 2; k8++) {
            uint4 a[MT];
            uint2 b[NT];
#pragma unroll
            for (int i = 0; i < MT; i++)
                a[i] = *(const uint4*)&Asu[((k8 * (BM/16) + wr*MT + i) * 32 + lane) * 4];
#pragma unroll
            for (int j = 0; j < NT; j++)
                b[j] = *(const uint2*)&Bsu[((k8 * (BN/8) + wc*NT + j) * 32 + lane) * 2];
#pragma unroll
            for (int i = 0; i < MT; i++)
#pragma unroll
                for (int j = 0; j < NT; j++)
                    mma_tf32(c[i][j], a[i].x, a[i].y, a[i].z, a[i].w, b[j].x, b[j].y);
        }
    }

    const bool split = (gridDim.z > 1);
    float* Co = C + (split ? (size_t)blockIdx.z * m_rows * CDIM : 0);
#pragma unroll
    for (int i = 0; i < MT; i++) {
#pragma unroll
        for (int j = 0; j < NT; j++) {
            int row = bm + wr*MT*16 + i*16 + (lane >> 2);
            int col = bn + wc*NT*8 + j*8 + ((lane & 3) << 1);
            float b00 = 0.f, b01 = 0.f, b10 = 0.f, b11 = 0.f;
            if (!split) {
                float2 b0 = *(const float2*)&GB[(size_t)row * CDIM + col];
                float2 b1 = *(const float2*)&GB[(size_t)(row + 8) * CDIM + col];
                b00 = b0.x; b01 = b0.y; b10 = b1.x; b11 = b1.y;
            }
            *(float2*)&Co[(size_t)row * CDIM + col] =
                make_float2(c[i][j][0] + b00, c[i][j][1] + b01);
            *(float2*)&Co[(size_t)(row + 8) * CDIM + col] =
                make_float2(c[i][j][2] + b10, c[i][j][3] + b11);
        }
    }
}

// ---------------- split-K reduce: out = sum_z part[z] + gbias ---------------
__global__ void __launch_bounds__(256) reduce_k(const float* __restrict__ part,
                                                const float* __restrict__ GB,
                                                float* __restrict__ out)
{
    int i = (blockIdx.x * 256 + threadIdx.x) << 2;
    float4 s = *(const float4*)&GB[i];
#pragma unroll
    for (int z = 0; z < KSPLIT; z++) {
        float4 p = *(const float4*)&part[(size_t)z * X_ELEMS + i];
        s.x += p.x; s.y += p.y; s.z += p.z; s.w += p.w;
    }
    *(float4*)&out[i] = s;
}

// ---------------- QK^T * scale via tf32 mma (64q x 128k x 64d one-shot) -----
__global__ void __launch_bounds__(256) qk_mma(const float* __restrict__ qp,
                                              const float* __restrict__ kp,
                                              float* __restrict__ attn)
{
    __shared__ float As[8 * 4  * 32 * 4];   // 4096 floats: Q  [k8][mt][lane][slot]
    __shared__ float Bs[8 * 16 * 32 * 2];   // 8192 floats: Kt [k8][nt][lane][slot]
    const int bh = blockIdx.z;
    const int b = bh >> 3, h = bh & 7;
    const int q0 = blockIdx.y << 6;
    const int k0 = blockIdx.x << 7;
    const int tid = threadIdx.x;
    const int w = tid >> 5, lane = tid & 31;
    const int wr = w >> 2, wc = w & 3;      // 2 x 4 warps, MT=2, NT=4

    // stage Q (scale folded in)
#pragma unroll
    for (int l = 0; l < 4; l++) {
        int idx = tid + l*256;
        int am = idx >> 4;
        int ak4 = (idx & 15) << 2;
        float4 v = *(const float4*)&qp[((size_t)(b*CLQ + q0 + am))*CDIM + h*CHEAD + ak4];
        int k8 = ak4 >> 3;
        int base = ((k8*4 + (am>>4))*32 + ((am&7)<<2))*4 + ((am>>3)&1) + 2*((ak4>>2)&1);
        As[base + 0]  = __uint_as_float(f2tf32(v.x * CSCALE));
        As[base + 4]  = __uint_as_float(f2tf32(v.y * CSCALE));
        As[base + 8]  = __uint_as_float(f2tf32(v.z * CSCALE));
        As[base + 12] = __uint_as_float(f2tf32(v.w * CSCALE));
    }
    // stage K tokens (operand B, n-major source [n][k])
#pragma unroll
    for (int l = 0; l < 8; l++) {
        int idx = tid + l*256;
        int n = idx >> 4;
        int bk4 = (idx & 15) << 2;
        float4 v = *(const float4*)&kp[((size_t)(b*CLKV + k0 + n))*CDIM + h*CHEAD + bk4];
        int k8 = bk4 >> 3;
        int base = ((k8*16 + (n>>3))*32 + ((n&7)<<2))*2 + ((bk4>>2)&1);
        Bs[base + 0] = __uint_as_float(f2tf32(v.x));
        Bs[base + 2] = __uint_as_float(f2tf32(v.y));
        Bs[base + 4] = __uint_as_float(f2tf32(v.z));
        Bs[base + 6] = __uint_as_float(f2tf32(v.w));
    }
    __syncthreads();

    const uint32_t* Asu = (const uint32_t*)As;
    const uint32_t* Bsu = (const uint32_t*)Bs;
    float c[2][4][4] = {};
#pragma unroll
    for (int k8 = 0; k8 < 8; k8++) {
        uint4 a[2];
        uint2 bb[4];
#pragma unroll
        for (int i = 0; i < 2; i++)
            a[i] = *(const uint4*)&Asu[((k8*4 + wr*2 + i)*32 + lane)*4];
#pragma unroll
        for (int j = 0; j < 4; j++)
            bb[j] = *(const uint2*)&Bsu[((k8*16 + wc*4 + j)*32 + lane)*2];
#pragma unroll
        for (int i = 0; i < 2; i++)
#pragma unroll
            for (int j = 0; j < 4; j++)
                mma_tf32(c[i][j], a[i].x, a[i].y, a[i].z, a[i].w, bb[j].x, bb[j].y);
    }
#pragma unroll
    for (int i = 0; i < 2; i++) {
#pragma unroll
        for (int j = 0; j < 4; j++) {
            int row = q0 + wr*32 + i*16 + (lane >> 2);
            int col = k0 + wc*32 + j*8 + ((lane & 3) << 1);
            *(float2*)&attn[((size_t)(bh*CLQ + row))*CLKV + col] =
                make_float2(c[i][j][0], c[i][j][1]);
            *(float2*)&attn[((size_t)(bh*CLQ + row + 8))*CLKV + col] =
                make_float2(c[i][j][2], c[i][j][3]);
        }
    }
}

// ---------------- row softmax over 4096, in place ---------------------------
__global__ void __launch_bounds__(256) softmax_kernel(float* __restrict__ attn)
{
    __shared__ float red[32];
    size_t row = (size_t)blockIdx.x * CLKV;
    int tid = threadIdx.x;
    float v[16];
    float m = -3.4e38f;
#pragma unroll
    for (int l = 0; l < 4; l++) {
        float4 x4 = *(const float4*)&attn[row + tid*4 + l*1024];
        v[l*4+0]=x4.x; v[l*4+1]=x4.y; v[l*4+2]=x4.z; v[l*4+3]=x4.w;
    }
#pragma unroll
    for (int i = 0; i < 16; i++) m = fmaxf(m, v[i]);
#pragma unroll
    for (int o = 16; o > 0; o >>= 1) m = fmaxf(m, __shfl_xor_sync(~0u, m, o));
    if ((tid & 31) == 0) red[tid >> 5] = m;
    __syncthreads();
    if (tid < 32) {
        float t = (tid < 8) ? red[tid] : -3.4e38f;
#pragma unroll
        for (int o = 4; o > 0; o >>= 1) t = fmaxf(t, __shfl_xor_sync(~0u, t, o));
        if (tid == 0) red[0] = t;
    }
    __syncthreads();
    m = red[0];
    float s = 0.f;
#pragma unroll
    for (int i = 0; i < 16; i++) { v[i] = __expf(v[i] - m); s += v[i]; }
#pragma unroll
    for (int o = 16; o > 0; o >>= 1) s += __shfl_xor_sync(~0u, s, o);
    __syncthreads();
    if ((tid & 31) == 0) red[tid >> 5] = s;
    __syncthreads();
    if (tid == 0) {
        float t = 0.f;
        for (int i = 0; i < 8; i++) t += red[i];
        red[0] = 1.f / t;
    }
    __syncthreads();
    float inv = red[0];
#pragma unroll
    for (int l = 0; l < 4; l++) {
        *(float4*)&attn[row + tid*4 + l*1024] =
            make_float4(v[l*4]*inv, v[l*4+1]*inv, v[l*4+2]*inv, v[l*4+3]*inv);
    }
}

// ---------------- P @ V via tf32 mma (64q x 64d, BK=32 loop over 4096) ------
__global__ void __launch_bounds__(256) av_mma(const float* __restrict__ attn,
                                              const float* __restrict__ vp,
                                              float* __restrict__ xbuf)
{
    __shared__ float As[4 * 4 * 32 * 4];   // 2048 floats: P
    __shared__ float Bs[4 * 8 * 32 * 2];   // 2048 floats: V
    const int bh = blockIdx.y;
    const int b = bh >> 3, h = bh & 7;
    const int q0 = blockIdx.x << 6;
    const int tid = threadIdx.x;
    const int w = tid >> 5, lane = tid & 31;
    const int wr = w >> 1, wc = w & 1;     // 4 x 2 warps, MT=1, NT=4

    int am[2], ak4[2], abase[2];
#pragma unroll
    for (int l = 0; l < 2; l++) {
        int idx = tid + l*256;
        am[l]  = idx >> 3;
        ak4[l] = (idx & 7) << 2;
        int k8 = ak4[l] >> 3;
        abase[l] = ((k8*4 + (am[l]>>4))*32 + ((am[l]&7)<<2))*4
                 + ((am[l]>>3)&1) + 2*((ak4[l]>>2)&1);
    }
    int br[2], bn4[2], bbase[2];
#pragma unroll
    for (int l = 0; l < 2; l++) {
        int idx = tid + l*256;
        br[l]  = idx >> 4;
        bn4[l] = (idx & 15) << 2;
        bbase[l] = (((br[l]>>3)*8 + (bn4[l]>>3))*32
                    + ((bn4[l]&7)<<2) + (br[l]&3))*2 + ((br[l]>>2)&1);
    }

    float4 pa[2], pb[2];
    auto load_tiles = [&](int k0) {
#pragma unroll
        for (int l = 0; l < 2; l++)
            pa[l] = *(const float4*)&attn[((size_t)(bh*CLQ + q0 + am[l]))*CLKV + k0 + ak4[l]];
#pragma unroll
        for (int l = 0; l < 2; l++)
            pb[l] = *(const float4*)&vp[((size_t)(b*CLKV + k0 + br[l]))*CDIM + h*CHEAD + bn4[l]];
    };

    float c[4][4] = {};
    const uint32_t* Asu = (const uint32_t*)As;
    const uint32_t* Bsu = (const uint32_t*)Bs;

    load_tiles(0);
    for (int k0 = 0; k0 < CLKV; k0 += 32) {
        __syncthreads();
#pragma unroll
        for (int l = 0; l < 2; l++) {
            As[abase[l] + 0]  = __uint_as_float(f2tf32(pa[l].x));
            As[abase[l] + 4]  = __uint_as_float(f2tf32(pa[l].y));
            As[abase[l] + 8]  = __uint_as_float(f2tf32(pa[l].z));
            As[abase[l] + 12] = __uint_as_float(f2tf32(pa[l].w));
        }
#pragma unroll
        for (int l = 0; l < 2; l++) {
            Bs[bbase[l] + 0]  = __uint_as_float(f2tf32(pb[l].x));
            Bs[bbase[l] + 8]  = __uint_as_float(f2tf32(pb[l].y));
            Bs[bbase[l] + 16] = __uint_as_float(f2tf32(pb[l].z));
            Bs[bbase[l] + 24] = __uint_as_float(f2tf32(pb[l].w));
        }
        __syncthreads();
        if (k0 + 32 < CLKV) load_tiles(k0 + 32);
#pragma unroll
        for (int k8 = 0; k8 < 4; k8++) {
            uint4 a = *(const uint4*)&Asu[((k8*4 + wr)*32 + lane)*4];
            uint2 bb[4];
#pragma unroll
            for (int j = 0; j < 4; j++)
                bb[j] = *(const uint2*)&Bsu[((k8*8 + wc*4 + j)*32 + lane)*2];
#pragma unroll
            for (int j = 0; j < 4; j++)
                mma_tf32(c[j], a.x, a.y, a.z, a.w, bb[j].x, bb[j].y);
        }
    }
#pragma unroll
    for (int j = 0; j < 4; j++) {
        int row = q0 + wr*16 + (lane >> 2);
        int col = h*CHEAD + wc*32 + j*8 + ((lane & 3) << 1);
        *(float2*)&xbuf[((size_t)(b*CLQ + row))*CDIM + col] =
            make_float2(c[j][0], c[j][1]);
        *(float2*)&xbuf[((size_t)(b*CLQ + row + 8))*CDIM + col] =
            make_float2(c[j][2], c[j][3]);
    }
}

// ---------------- launch ----------------------------------------------------
extern "C" void kernel_launch(void* const* d_in, const int* in_sizes, int n_in,
                              void* d_out, int out_size)
{
    const float* q    = (const float*)d_in[0];
    const float* kv   = (const float*)d_in[1];
    const float* q_gw = (const float*)d_in[2];
    const float* q_gb = (const float*)d_in[3];
    const float* q_w  = (const float*)d_in[4];
    const float* q_b  = (const float*)d_in[5];
    const float* k_gw = (const float*)d_in[6];
    const float* k_gb = (const float*)d_in[7];
    const float* k_w  = (const float*)d_in[8];
    const float* k_b  = (const float*)d_in[9];
    const float* v_gw = (const float*)d_in[10];
    const float* v_gb = (const float*)d_in[11];
    const float* v_w  = (const float*)d_in[12];
    const float* v_b  = (const float*)d_in[13];
    const float* o_gw = (const float*)d_in[14];
    const float* o_gb = (const float*)d_in[15];
    const float* o_w  = (const float*)d_in[16];
    const float* o_b  = (const float*)d_in[17];
    float* out = (float*)d_out;

    static float *qp=nullptr,*kp=nullptr,*vp=nullptr,*xbuf=nullptr;
    static float *gq=nullptr,*gk=nullptr,*gv=nullptr,*go=nullptr,*afb=nullptr;
    static float *gbq=nullptr,*gbk=nullptr,*gbv=nullptr,*gbo=nullptr,*part=nullptr;
    if (!qp) {
        cudaGetSymbolAddress((void**)&qp,   g_qp);
        cudaGetSymbolAddress((void**)&kp,   g_kp);
        cudaGetSymbolAddress((void**)&vp,   g_vp);
        cudaGetSymbolAddress((void**)&xbuf, g_xbuf);
        cudaGetSymbolAddress((void**)&gq,   g_gq);
        cudaGetSymbolAddress((void**)&gk,   g_gk);
        cudaGetSymbolAddress((void**)&gv,   g_gv);
        cudaGetSymbolAddress((void**)&go,   g_go);
        cudaGetSymbolAddress((void**)&afb,  g_attn_fb);
        cudaGetSymbolAddress((void**)&gbq,  g_gbq);
        cudaGetSymbolAddress((void**)&gbk,  g_gbk);
        cudaGetSymbolAddress((void**)&gbv,  g_gbv);
        cudaGetSymbolAddress((void**)&gbo,  g_gbo);
        cudaGetSymbolAddress((void**)&part, g_part);
    }
    // output layout: x (524288 floats) then attn (33554432 floats)
    float* attn = (out_size >= (X_ELEMS + ATTN_ELEMS)) ? (out + X_ELEMS) : afb;

    gate_kernel<<<CTQ/8, 256>>>(q,  q_gw, q_gb, q_b, gq, gbq, CTQ);
    gate_kernel<<<CTKV/8, 256>>>(kv, k_gw, k_gb, k_b, gk, gbk, CTKV);
    gate_kernel<<<CTKV/8, 256>>>(kv, v_gw, v_gb, v_b, gv, gbv, CTKV);

    // Q projection: split-K over 4 slices of 1280, then reduce(+gbias)
    moe_mma<64,64,2,2><<<dim3(CDIM/64, CTQ/64, KSPLIT), 128>>>(q, gq, q_w, gbq, part, CK/KSPLIT, CTQ);
    reduce_k<<<X_ELEMS/1024, 256>>>(part, gbq, qp);

    moe_mma<128,128,2,4><<<dim3(CDIM/128, CTKV/128, 1), 256>>>(kv, gk, k_w, gbk, kp, CK, CTKV);
    moe_mma<128,128,2,4><<<dim3(CDIM/128, CTKV/128, 1), 256>>>(kv, gv, v_w, gbv, vp, CK, CTKV);

    qk_mma<<<dim3(CLKV/128, CLQ/64, CB*CH), 256>>>(qp, kp, attn);
    softmax_kernel<<<CB*CH*CLQ, 256>>>(attn);
    av_mma<<<dim3(CLQ/64, CB*CH), 256>>>(attn, vp, xbuf);

    gate_kernel<<<CTQ/8, 256>>>(xbuf, o_gw, o_gb, o_b, go, gbo, CTQ);

    // O projection: split-K as well
    moe_mma<64,64,2,2><<<dim3(CDIM/64, CTQ/64, KSPLIT), 128>>>(xbuf, go, o_w, gbo, part, CK/KSPLIT, CTQ);
    reduce_k<<<X_ELEMS/1024, 256>>>(part, gbo, out);
}

// round 6
// speedup vs baseline: 1.5021x; 1.0241x over previous
#include <cuda_runtime.h>
#include <math.h>
#include <stdint.h>

#define CB 2
#define CLQ 512
#define CLKV 4096
#define CDIM 512
#define CH 8
#define CE 10
#define CTOPK 5
#define CHEAD 64
#define CTQ (CB*CLQ)      /* 1024 */
#define CTKV (CB*CLKV)    /* 8192 */
#define CK (CE*CDIM)      /* 5120 */
#define CSCALE 0.125f
#define X_ELEMS (CTQ*CDIM)              /* 524288 */
#define ATTN_ELEMS (CB*CH*CLQ*CLKV)     /* 33554432 */
#define KSPLIT 4
#define AVSPLIT 4

// ---------------- scratch (static device globals) ---------------------------
__device__ float g_qp[CTQ*CDIM];
__device__ float g_kp[CTKV*CDIM];
__device__ float g_vp[CTKV*CDIM];
__device__ float g_xbuf[CTQ*CDIM];
__device__ float g_gq[CTQ*CE];
__device__ float g_gk[CTKV*CE];
__device__ float g_gv[CTKV*CE];
__device__ float g_go[CTQ*CE];
__device__ float g_gbq[CTQ*CDIM];
__device__ float g_gbk[CTKV*CDIM];
__device__ float g_gbv[CTKV*CDIM];
__device__ float g_gbo[CTQ*CDIM];
__device__ float g_part[KSPLIT*CTQ*CDIM];
__device__ float g_attn_fb[ATTN_ELEMS];

// ---------------- helpers ---------------------------------------------------
__device__ __forceinline__ uint32_t f2tf32(float x) {
    uint32_t u;
    asm("cvt.rna.tf32.f32 %0, %1;" : "=r"(u) : "f"(x));
    return u;
}

__device__ __forceinline__ void mma_tf32(float c[4],
                                         uint32_t a0, uint32_t a1, uint32_t a2, uint32_t a3,
                                         uint32_t b0, uint32_t b1) {
    asm volatile(
        "mma.sync.aligned.m16n8k8.row.col.f32.tf32.tf32.f32 "
        "{%0,%1,%2,%3}, {%4,%5,%6,%7}, {%8,%9}, {%0,%1,%2,%3};"
        : "+f"(c[0]), "+f"(c[1]), "+f"(c[2]), "+f"(c[3])
        : "r"(a0), "r"(a1), "r"(a2), "r"(a3), "r"(b0), "r"(b1));
}

// ---------------- gate: softmax -> top-5 -> renorm + gbias (warp/token) -----
__global__ void gate_kernel(const float* __restrict__ x,
                            const float* __restrict__ gw,   // [512, E]
                            const float* __restrict__ gb,   // [E]
                            const float* __restrict__ bias, // [E, 512]
                            float* __restrict__ g,          // [T, E]
                            float* __restrict__ gbias,      // [T, 512]
                            int T)
{
    int tok  = (blockIdx.x * blockDim.x + threadIdx.x) >> 5;
    int lane = threadIdx.x & 31;
    if (tok >= T) return;
    const float* xr = x + (size_t)tok * CDIM;
    float acc[CE];
#pragma unroll
    for (int e = 0; e < CE; e++) acc[e] = 0.f;
    for (int i = lane; i < CDIM; i += 32) {
        float xv = xr[i];
        const float* gr = gw + (size_t)i * CE;
#pragma unroll
        for (int e = 0; e < CE; e++) acc[e] += xv * gr[e];
    }
#pragma unroll
    for (int e = 0; e < CE; e++) {
#pragma unroll
        for (int o = 16; o > 0; o >>= 1)
            acc[e] += __shfl_xor_sync(0xffffffffu, acc[e], o);
    }
    float outv[CE];
#pragma unroll
    for (int e = 0; e < CE; e++) outv[e] = 0.f;
    if (lane == 0) {
        float l[CE];
#pragma unroll
        for (int e = 0; e < CE; e++) l[e] = acc[e] + gb[e];
        bool used[CE];
#pragma unroll
        for (int e = 0; e < CE; e++) used[e] = false;
        int sel[CTOPK];
        float m = -3.4e38f;
        for (int k = 0; k < CTOPK; k++) {          // strict >: first index wins ties
            int best = 0; float bv = -3.4e38f;
            for (int e = 0; e < CE; e++)
                if (!used[e] && l[e] > bv) { bv = l[e]; best = e; }
            used[best] = true; sel[k] = best;
            if (k == 0) m = bv;
        }
        float ex[CTOPK]; float s = 0.f;
        for (int k = 0; k < CTOPK; k++) { ex[k] = __expf(l[sel[k]] - m); s += ex[k]; }
        float inv = 1.f / s;
        for (int k = 0; k < CTOPK; k++) outv[sel[k]] = ex[k] * inv;
        float* gr = g + (size_t)tok * CE;
        for (int e = 0; e < CE; e++) gr[e] = outv[e];
    }
    __syncwarp();
    float ge[CE];
#pragma unroll
    for (int e = 0; e < CE; e++) ge[e] = __shfl_sync(0xffffffffu, outv[e], 0);
    float* gbo = gbias + (size_t)tok * CDIM;
#pragma unroll
    for (int c0 = 0; c0 < CDIM; c0 += 32) {
        int c = c0 + lane;
        float s = 0.f;
#pragma unroll
        for (int e = 0; e < CE; e++) s += ge[e] * bias[e*CDIM + c];
        gbo[c] = s;
    }
}

// --------- tf32 tensor-core MoE GEMM, double-buffered smem, split-K capable -
// C[M,512] = A'(g*x)[M,5120] @ W[5120,512] (+ gbias if not split)
template<int BM, int BN, int WR, int WC>
__global__ void __launch_bounds__(WR*WC*32) moe_mma(const float* __restrict__ X,
                                                    const float* __restrict__ G,
                                                    const float* __restrict__ W,
                                                    const float* __restrict__ GB,
                                                    float* __restrict__ C,
                                                    int klen, int m_rows)
{
    constexpr int THREADS = WR * WC * 32;
    constexpr int MT = BM / WR / 16;
    constexpr int NT = BN / WC / 8;
    constexpr int LA = BM * 4 / THREADS;
    constexpr int LB = BN * 4 / THREADS;
    static_assert(LA == 2 && LB == 2, "staging assumes 2 loads per thread");
    constexpr int ASZ = 2 * (BM/16) * 32 * 4;   // floats per stage
    constexpr int BSZ = 2 * (BN/8)  * 32 * 2;

    __shared__ float As[2 * ASZ];
    __shared__ float Bs[2 * BSZ];

    const int tid  = threadIdx.x;
    const int w    = tid >> 5;
    const int lane = tid & 31;
    const int wr   = w / WC;
    const int wc   = w % WC;
    const int bm   = blockIdx.y * BM;
    const int bn   = blockIdx.x * BN;
    const int kbeg = blockIdx.z * klen;
    const int kend = kbeg + klen;

    int am[LA], ak4[LA], abase[LA];
#pragma unroll
    for (int l = 0; l < LA; l++) {
        int idx = tid + l * THREADS;
        am[l]  = idx >> 2;
        ak4[l] = (idx & 3) << 2;
        int k8 = ak4[l] >> 3;
        int mt = am[l] >> 4;
        abase[l] = ((k8 * (BM/16) + mt) * 32 + ((am[l] & 7) << 2)) * 4
                 + ((am[l] >> 3) & 1) + 2 * ((ak4[l] >> 2) & 1);
    }
    int br[LB], bn4[LB], bbase[LB];
#pragma unroll
    for (int l = 0; l < LB; l++) {
        int idx = tid + l * THREADS;
        br[l]  = idx / (BN/4);
        bn4[l] = (idx % (BN/4)) << 2;
        bbase[l] = (((br[l] >> 3) * (BN/8) + (bn4[l] >> 3)) * 32
                    + ((bn4[l] & 7) << 2) + (br[l] & 3)) * 2 + ((br[l] >> 2) & 1);
    }

    float4 pa[LA], pb[LB];
    float  ga[LA];
    auto load_tiles = [&](int k0) {
#pragma unroll
        for (int l = 0; l < LA; l++) {
            pa[l] = *(const float4*)&X[(size_t)(bm + am[l]) * CDIM + (k0 & 511) + ak4[l]];
            ga[l] = G[(size_t)(bm + am[l]) * CE + (k0 >> 9)];
        }
#pragma unroll
        for (int l = 0; l < LB; l++)
            pb[l] = *(const float4*)&W[(size_t)(k0 + br[l]) * CDIM + bn + bn4[l]];
    };
    auto stage = [&](float* Ap, float* Bp) {
#pragma unroll
        for (int l = 0; l < LA; l++) {
            float g = ga[l];
            Ap[abase[l] + 0]  = __uint_as_float(f2tf32(pa[l].x * g));
            Ap[abase[l] + 4]  = __uint_as_float(f2tf32(pa[l].y * g));
            Ap[abase[l] + 8]  = __uint_as_float(f2tf32(pa[l].z * g));
            Ap[abase[l] + 12] = __uint_as_float(f2tf32(pa[l].w * g));
        }
#pragma unroll
        for (int l = 0; l < LB; l++) {
            Bp[bbase[l] + 0]  = __uint_as_float(f2tf32(pb[l].x));
            Bp[bbase[l] + 8]  = __uint_as_float(f2tf32(pb[l].y));
            Bp[bbase[l] + 16] = __uint_as_float(f2tf32(pb[l].z));
            Bp[bbase[l] + 24] = __uint_as_float(f2tf32(pb[l].w));
        }
    };

    float c[MT][NT][4] = {};

    load_tiles(kbeg);
    stage(As, Bs);
    if (kbeg + 16 < kend) load_tiles(kbeg + 16);
    __syncthreads();

    for (int k0 = kbeg; k0 < kend; k0 += 16) {
        const int p = ((k0 - kbeg) >> 4) & 1;
        const uint32_t* Asu = (const uint32_t*)(As + p * ASZ);
        const uint32_t* Bsu = (const uint32_t*)(Bs + p * BSZ);
        if (k0 + 16 < kend) {
            stage(As + (p^1) * ASZ, Bs + (p^1) * BSZ);   // regs hold k0+16
            if (k0 + 32 < kend) load_tiles(k0 + 32);
        }
#pragma unroll
        for (int k8 = 0; k8 < 2; k8++) {
            uint4 a[MT];
            uint2 b[NT];
#pragma unroll
            for (int i = 0; i < MT; i++)
                a[i] = *(const uint4*)&Asu[((k8 * (BM/16) + wr*MT + i) * 32 + lane) * 4];
#pragma unroll
            for (int j = 0; j < NT; j++)
                b[j] = *(const uint2*)&Bsu[((k8 * (BN/8) + wc*NT + j) * 32 + lane) * 2];
#pragma unroll
            for (int i = 0; i < MT; i++)
#pragma unroll
                for (int j = 0; j < NT; j++)
                    mma_tf32(c[i][j], a[i].x, a[i].y, a[i].z, a[i].w, b[j].x, b[j].y);
        }
        __syncthreads();
    }

    const bool split = (gridDim.z > 1);
    float* Co = C + (split ? (size_t)blockIdx.z * m_rows * CDIM : 0);
#pragma unroll
    for (int i = 0; i < MT; i++) {
#pragma unroll
        for (int j = 0; j < NT; j++) {
            int row = bm + wr*MT*16 + i*16 + (lane >> 2);
            int col = bn + wc*NT*8 + j*8 + ((lane & 3) << 1);
            float b00 = 0.f, b01 = 0.f, b10 = 0.f, b11 = 0.f;
            if (!split) {
                float2 b0 = *(const float2*)&GB[(size_t)row * CDIM + col];
                float2 b1 = *(const float2*)&GB[(size_t)(row + 8) * CDIM + col];
                b00 = b0.x; b01 = b0.y; b10 = b1.x; b11 = b1.y;
            }
            *(float2*)&Co[(size_t)row * CDIM + col] =
                make_float2(c[i][j][0] + b00, c[i][j][1] + b01);
            *(float2*)&Co[(size_t)(row + 8) * CDIM + col] =
                make_float2(c[i][j][2] + b10, c[i][j][3] + b11);
        }
    }
}

// ---------------- split-K reduce: out = sum_z part[z] + gbias ---------------
__global__ void __launch_bounds__(256) reduce_k(const float* __restrict__ part,
                                                const float* __restrict__ GB,
                                                float* __restrict__ out)
{
    int i = (blockIdx.x * 256 + threadIdx.x) << 2;
    float4 s = *(const float4*)&GB[i];
#pragma unroll
    for (int z = 0; z < KSPLIT; z++) {
        float4 p = *(const float4*)&part[(size_t)z * X_ELEMS + i];
        s.x += p.x; s.y += p.y; s.z += p.z; s.w += p.w;
    }
    *(float4*)&out[i] = s;
}

__global__ void __launch_bounds__(256) reduce_av(const float* __restrict__ part,
                                                 float* __restrict__ out)
{
    int i = (blockIdx.x * 256 + threadIdx.x) << 2;
    float4 s = *(const float4*)&part[i];
#pragma unroll
    for (int z = 1; z < AVSPLIT; z++) {
        float4 p = *(const float4*)&part[(size_t)z * X_ELEMS + i];
        s.x += p.x; s.y += p.y; s.z += p.z; s.w += p.w;
    }
    *(float4*)&out[i] = s;
}

// ---------------- QK^T * scale via tf32 mma (64q x 128k x 64d one-shot) -----
__global__ void __launch_bounds__(256) qk_mma(const float* __restrict__ qp,
                                              const float* __restrict__ kp,
                                              float* __restrict__ attn)
{
    __shared__ float As[8 * 4  * 32 * 4];
    __shared__ float Bs[8 * 16 * 32 * 2];
    const int bh = blockIdx.z;
    const int b = bh >> 3, h = bh & 7;
    const int q0 = blockIdx.y << 6;
    const int k0 = blockIdx.x << 7;
    const int tid = threadIdx.x;
    const int w = tid >> 5, lane = tid & 31;
    const int wr = w >> 2, wc = w & 3;      // 2 x 4 warps, MT=2, NT=4

#pragma unroll
    for (int l = 0; l < 4; l++) {
        int idx = tid + l*256;
        int am = idx >> 4;
        int ak4 = (idx & 15) << 2;
        float4 v = *(const float4*)&qp[((size_t)(b*CLQ + q0 + am))*CDIM + h*CHEAD + ak4];
        int k8 = ak4 >> 3;
        int base = ((k8*4 + (am>>4))*32 + ((am&7)<<2))*4 + ((am>>3)&1) + 2*((ak4>>2)&1);
        As[base + 0]  = __uint_as_float(f2tf32(v.x * CSCALE));
        As[base + 4]  = __uint_as_float(f2tf32(v.y * CSCALE));
        As[base + 8]  = __uint_as_float(f2tf32(v.z * CSCALE));
        As[base + 12] = __uint_as_float(f2tf32(v.w * CSCALE));
    }
#pragma unroll
    for (int l = 0; l < 8; l++) {
        int idx = tid + l*256;
        int n = idx >> 4;
        int bk4 = (idx & 15) << 2;
        float4 v = *(const float4*)&kp[((size_t)(b*CLKV + k0 + n))*CDIM + h*CHEAD + bk4];
        int k8 = bk4 >> 3;
        int base = ((k8*16 + (n>>3))*32 + ((n&7)<<2))*2 + ((bk4>>2)&1);
        Bs[base + 0] = __uint_as_float(f2tf32(v.x));
        Bs[base + 2] = __uint_as_float(f2tf32(v.y));
        Bs[base + 4] = __uint_as_float(f2tf32(v.z));
        Bs[base + 6] = __uint_as_float(f2tf32(v.w));
    }
    __syncthreads();

    const uint32_t* Asu = (const uint32_t*)As;
    const uint32_t* Bsu = (const uint32_t*)Bs;
    float c[2][4][4] = {};
#pragma unroll
    for (int k8 = 0; k8 < 8; k8++) {
        uint4 a[2];
        uint2 bb[4];
#pragma unroll
        for (int i = 0; i < 2; i++)
            a[i] = *(const uint4*)&Asu[((k8*4 + wr*2 + i)*32 + lane)*4];
#pragma unroll
        for (int j = 0; j < 4; j++)
            bb[j] = *(const uint2*)&Bsu[((k8*16 + wc*4 + j)*32 + lane)*2];
#pragma unroll
        for (int i = 0; i < 2; i++)
#pragma unroll
            for (int j = 0; j < 4; j++)
                mma_tf32(c[i][j], a[i].x, a[i].y, a[i].z, a[i].w, bb[j].x, bb[j].y);
    }
#pragma unroll
    for (int i = 0; i < 2; i++) {
#pragma unroll
        for (int j = 0; j < 4; j++) {
            int row = q0 + wr*32 + i*16 + (lane >> 2);
            int col = k0 + wc*32 + j*8 + ((lane & 3) << 1);
            *(float2*)&attn[((size_t)(bh*CLQ + row))*CLKV + col] =
                make_float2(c[i][j][0], c[i][j][1]);
            *(float2*)&attn[((size_t)(bh*CLQ + row + 8))*CLKV + col] =
                make_float2(c[i][j][2], c[i][j][3]);
        }
    }
}

// ---------------- row softmax over 4096, in place ---------------------------
__global__ void __launch_bounds__(256) softmax_kernel(float* __restrict__ attn)
{
    __shared__ float red[32];
    size_t row = (size_t)blockIdx.x * CLKV;
    int tid = threadIdx.x;
    float v[16];
    float m = -3.4e38f;
#pragma unroll
    for (int l = 0; l < 4; l++) {
        float4 x4 = *(const float4*)&attn[row + tid*4 + l*1024];
        v[l*4+0]=x4.x; v[l*4+1]=x4.y; v[l*4+2]=x4.z; v[l*4+3]=x4.w;
    }
#pragma unroll
    for (int i = 0; i < 16; i++) m = fmaxf(m, v[i]);
#pragma unroll
    for (int o = 16; o > 0; o >>= 1) m = fmaxf(m, __shfl_xor_sync(~0u, m, o));
    if ((tid & 31) == 0) red[tid >> 5] = m;
    __syncthreads();
    if (tid < 32) {
        float t = (tid < 8) ? red[tid] : -3.4e38f;
#pragma unroll
        for (int o = 4; o > 0; o >>= 1) t = fmaxf(t, __shfl_xor_sync(~0u, t, o));
        if (tid == 0) red[0] = t;
    }
    __syncthreads();
    m = red[0];
    float s = 0.f;
#pragma unroll
    for (int i = 0; i < 16; i++) { v[i] = __expf(v[i] - m); s += v[i]; }
#pragma unroll
    for (int o = 16; o > 0; o >>= 1) s += __shfl_xor_sync(~0u, s, o);
    __syncthreads();
    if ((tid & 31) == 0) red[tid >> 5] = s;
    __syncthreads();
    if (tid == 0) {
        float t = 0.f;
        for (int i = 0; i < 8; i++) t += red[i];
        red[0] = 1.f / t;
    }
    __syncthreads();
    float inv = red[0];
#pragma unroll
    for (int l = 0; l < 4; l++) {
        *(float4*)&attn[row + tid*4 + l*1024] =
            make_float4(v[l*4]*inv, v[l*4+1]*inv, v[l*4+2]*inv, v[l*4+3]*inv);
    }
}

// ---------------- P @ V via tf32 mma, split-K over KV, double-buffered ------
__global__ void __launch_bounds__(256) av_mma(const float* __restrict__ attn,
                                              const float* __restrict__ vp,
                                              float* __restrict__ part)
{
    constexpr int ASZ = 4 * 4 * 32 * 4;   // 2048 floats per stage
    constexpr int BSZ = 4 * 8 * 32 * 2;   // 2048 floats per stage
    __shared__ float As[2 * ASZ];
    __shared__ float Bs[2 * BSZ];
    const int bh = blockIdx.y;
    const int b = bh >> 3, h = bh & 7;
    const int q0 = blockIdx.x << 6;
    const int kbeg = blockIdx.z * (CLKV / AVSPLIT);
    const int kend = kbeg + (CLKV / AVSPLIT);
    const int tid = threadIdx.x;
    const int w = tid >> 5, lane = tid & 31;
    const int wr = w >> 1, wc = w & 1;     // 4 x 2 warps, MT=1, NT=4

    int am[2], ak4[2], abase[2];
#pragma unroll
    for (int l = 0; l < 2; l++) {
        int idx = tid + l*256;
        am[l]  = idx >> 3;
        ak4[l] = (idx & 7) << 2;
        int k8 = ak4[l] >> 3;
        abase[l] = ((k8*4 + (am[l]>>4))*32 + ((am[l]&7)<<2))*4
                 + ((am[l]>>3)&1) + 2*((ak4[l]>>2)&1);
    }
    int br[2], bn4[2], bbase[2];
#pragma unroll
    for (int l = 0; l < 2; l++) {
        int idx = tid + l*256;
        br[l]  = idx >> 4;
        bn4[l] = (idx & 15) << 2;
        bbase[l] = (((br[l]>>3)*8 + (bn4[l]>>3))*32
                    + ((bn4[l]&7)<<2) + (br[l]&3))*2 + ((br[l]>>2)&1);
    }

    float4 pa[2], pb[2];
    auto load_tiles = [&](int k0) {
#pragma unroll
        for (int l = 0; l < 2; l++)
            pa[l] = *(const float4*)&attn[((size_t)(bh*CLQ + q0 + am[l]))*CLKV + k0 + ak4[l]];
#pragma unroll
        for (int l = 0; l < 2; l++)
            pb[l] = *(const float4*)&vp[((size_t)(b*CLKV + k0 + br[l]))*CDIM + h*CHEAD + bn4[l]];
    };
    auto stage = [&](float* Ap, float* Bp) {
#pragma unroll
        for (int l = 0; l < 2; l++) {
            Ap[abase[l] + 0]  = __uint_as_float(f2tf32(pa[l].x));
            Ap[abase[l] + 4]  = __uint_as_float(f2tf32(pa[l].y));
            Ap[abase[l] + 8]  = __uint_as_float(f2tf32(pa[l].z));
            Ap[abase[l] + 12] = __uint_as_float(f2tf32(pa[l].w));
        }
#pragma unroll
        for (int l = 0; l < 2; l++) {
            Bp[bbase[l] + 0]  = __uint_as_float(f2tf32(pb[l].x));
            Bp[bbase[l] + 8]  = __uint_as_float(f2tf32(pb[l].y));
            Bp[bbase[l] + 16] = __uint_as_float(f2tf32(pb[l].z));
            Bp[bbase[l] + 24] = __uint_as_float(f2tf32(pb[l].w));
        }
    };

    float c[4][4] = {};

    load_tiles(kbeg);
    stage(As, Bs);
    if (kbeg + 32 < kend) load_tiles(kbeg + 32);
    __syncthreads();

    for (int k0 = kbeg; k0 < kend; k0 += 32) {
        const int p = ((k0 - kbeg) >> 5) & 1;
        const uint32_t* Asu = (const uint32_t*)(As + p * ASZ);
        const uint32_t* Bsu = (const uint32_t*)(Bs + p * BSZ);
        if (k0 + 32 < kend) {
            stage(As + (p^1)*ASZ, Bs + (p^1)*BSZ);
            if (k0 + 64 < kend) load_tiles(k0 + 64);
        }
#pragma unroll
        for (int k8 = 0; k8 < 4; k8++) {
            uint4 a = *(const uint4*)&Asu[((k8*4 + wr)*32 + lane)*4];
            uint2 bb[4];
#pragma unroll
            for (int j = 0; j < 4; j++)
                bb[j] = *(const uint2*)&Bsu[((k8*8 + wc*4 + j)*32 + lane)*2];
#pragma unroll
            for (int j = 0; j < 4; j++)
                mma_tf32(c[j], a.x, a.y, a.z, a.w, bb[j].x, bb[j].y);
        }
        __syncthreads();
    }
    float* Co = part + (size_t)blockIdx.z * X_ELEMS;
#pragma unroll
    for (int j = 0; j < 4; j++) {
        int row = q0 + wr*16 + (lane >> 2);
        int col = h*CHEAD + wc*32 + j*8 + ((lane & 3) << 1);
        *(float2*)&Co[((size_t)(b*CLQ + row))*CDIM + col] =
            make_float2(c[j][0], c[j][1]);
        *(float2*)&Co[((size_t)(b*CLQ + row + 8))*CDIM + col] =
            make_float2(c[j][2], c[j][3]);
    }
}

// ---------------- launch ----------------------------------------------------
extern "C" void kernel_launch(void* const* d_in, const int* in_sizes, int n_in,
                              void* d_out, int out_size)
{
    const float* q    = (const float*)d_in[0];
    const float* kv   = (const float*)d_in[1];
    const float* q_gw = (const float*)d_in[2];
    const float* q_gb = (const float*)d_in[3];
    const float* q_w  = (const float*)d_in[4];
    const float* q_b  = (const float*)d_in[5];
    const float* k_gw = (const float*)d_in[6];
    const float* k_gb = (const float*)d_in[7];
    const float* k_w  = (const float*)d_in[8];
    const float* k_b  = (const float*)d_in[9];
    const float* v_gw = (const float*)d_in[10];
    const float* v_gb = (const float*)d_in[11];
    const float* v_w  = (const float*)d_in[12];
    const float* v_b  = (const float*)d_in[13];
    const float* o_gw = (const float*)d_in[14];
    const float* o_gb = (const float*)d_in[15];
    const float* o_w  = (const float*)d_in[16];
    const float* o_b  = (const float*)d_in[17];
    float* out = (float*)d_out;

    static float *qp=nullptr,*kp=nullptr,*vp=nullptr,*xbuf=nullptr;
    static float *gq=nullptr,*gk=nullptr,*gv=nullptr,*go=nullptr,*afb=nullptr;
    static float *gbq=nullptr,*gbk=nullptr,*gbv=nullptr,*gbo=nullptr,*part=nullptr;
    if (!qp) {
        cudaGetSymbolAddress((void**)&qp,   g_qp);
        cudaGetSymbolAddress((void**)&kp,   g_kp);
        cudaGetSymbolAddress((void**)&vp,   g_vp);
        cudaGetSymbolAddress((void**)&xbuf, g_xbuf);
        cudaGetSymbolAddress((void**)&gq,   g_gq);
        cudaGetSymbolAddress((void**)&gk,   g_gk);
        cudaGetSymbolAddress((void**)&gv,   g_gv);
        cudaGetSymbolAddress((void**)&go,   g_go);
        cudaGetSymbolAddress((void**)&afb,  g_attn_fb);
        cudaGetSymbolAddress((void**)&gbq,  g_gbq);
        cudaGetSymbolAddress((void**)&gbk,  g_gbk);
        cudaGetSymbolAddress((void**)&gbv,  g_gbv);
        cudaGetSymbolAddress((void**)&gbo,  g_gbo);
        cudaGetSymbolAddress((void**)&part, g_part);
    }
    // output layout: x (524288 floats) then attn (33554432 floats)
    float* attn = (out_size >= (X_ELEMS + ATTN_ELEMS)) ? (out + X_ELEMS) : afb;

    gate_kernel<<<CTQ/8, 256>>>(q,  q_gw, q_gb, q_b, gq, gbq, CTQ);
    gate_kernel<<<CTKV/8, 256>>>(kv, k_gw, k_gb, k_b, gk, gbk, CTKV);
    gate_kernel<<<CTKV/8, 256>>>(kv, v_gw, v_gb, v_b, gv, gbv, CTKV);

    // Q projection: split-K over 4 slices of 1280, then reduce(+gbias)
    moe_mma<64,64,2,2><<<dim3(CDIM/64, CTQ/64, KSPLIT), 128>>>(q, gq, q_w, gbq, part, CK/KSPLIT, CTQ);
    reduce_k<<<X_ELEMS/1024, 256>>>(part, gbq, qp);

    moe_mma<128,128,2,4><<<dim3(CDIM/128, CTKV/128, 1), 256>>>(kv, gk, k_w, gbk, kp, CK, CTKV);
    moe_mma<128,128,2,4><<<dim3(CDIM/128, CTKV/128, 1), 256>>>(kv, gv, v_w, gbv, vp, CK, CTKV);

    qk_mma<<<dim3(CLKV/128, CLQ/64, CB*CH), 256>>>(qp, kp, attn);
    softmax_kernel<<<CB*CH*CLQ, 256>>>(attn);

    av_mma<<<dim3(CLQ/64, CB*CH, AVSPLIT), 256>>>(attn, vp, part);
    reduce_av<<<X_ELEMS/1024, 256>>>(part, xbuf);

    gate_kernel<<<CTQ/8, 256>>>(xbuf, o_gw, o_gb, o_b, go, gbo, CTQ);

    // O projection: split-K as well
    moe_mma<64,64,2,2><<<dim3(CDIM/64, CTQ/64, KSPLIT), 128>>>(xbuf, go, o_w, gbo, part, CK/KSPLIT, CTQ);
    reduce_k<<<X_ELEMS/1024, 256>>>(part, gbo, out);
}

// round 10
// speedup vs baseline: 1.6372x; 1.0899x over previous
#include <cuda_runtime.h>
#include <math.h>
#include <stdint.h>

#define CB 2
#define CLQ 512
#define CLKV 4096
#define CDIM 512
#define CH 8
#define CE 10
#define CTOPK 5
#define CHEAD 64
#define CTQ (CB*CLQ)      /* 1024 */
#define CTKV (CB*CLKV)    /* 8192 */
#define CK (CE*CDIM)      /* 5120 */
#define CSCALE 0.125f
#define X_ELEMS (CTQ*CDIM)              /* 524288 */
#define ATTN_ELEMS (CB*CH*CLQ*CLKV)     /* 33554432 */
#define KSPLIT 8
#define AVSPLIT 8

// ---------------- scratch (static device globals) ---------------------------
__device__ float g_qp[CTQ*CDIM];
__device__ float g_kp[CTKV*CDIM];
__device__ float g_vp[CTKV*CDIM];
__device__ float g_xbuf[CTQ*CDIM];
__device__ float g_gq[CTQ*CE];
__device__ float g_gk[CTKV*CE];
__device__ float g_gv[CTKV*CE];
__device__ float g_go[CTQ*CE];
__device__ float g_gbk[CTKV*CDIM];
__device__ float g_gbv[CTKV*CDIM];
__device__ float g_part[KSPLIT*CTQ*CDIM];
__device__ float g_attn_fb[ATTN_ELEMS];

// ---------------- helpers ---------------------------------------------------
__device__ __forceinline__ uint32_t f2tf32(float x) {
    uint32_t u;
    asm("cvt.rna.tf32.f32 %0, %1;" : "=r"(u) : "f"(x));
    return u;
}

__device__ __forceinline__ void mma_tf32(float c[4],
                                         uint32_t a0, uint32_t a1, uint32_t a2, uint32_t a3,
                                         uint32_t b0, uint32_t b1) {
    asm volatile(
        "mma.sync.aligned.m16n8k8.row.col.f32.tf32.tf32.f32 "
        "{%0,%1,%2,%3}, {%4,%5,%6,%7}, {%8,%9}, {%0,%1,%2,%3};"
        : "+f"(c[0]), "+f"(c[1]), "+f"(c[2]), "+f"(c[3])
        : "r"(a0), "r"(a1), "r"(a2), "r"(a3), "r"(b0), "r"(b1));
}

// ---------------- gate: softmax -> top-5 -> renormalize (warp/token) --------
__global__ void gate_kernel(const float* __restrict__ x,
                            const float* __restrict__ gw,   // [512, E]
                            const float* __restrict__ gb,   // [E]
                            float* __restrict__ g,          // [T, E]
                            int T)
{
    int tok  = (blockIdx.x * blockDim.x + threadIdx.x) >> 5;
    int lane = threadIdx.x & 31;
    if (tok >= T) return;
    const float* xr = x + (size_t)tok * CDIM;
    float acc[CE];
#pragma unroll
    for (int e = 0; e < CE; e++) acc[e] = 0.f;
    for (int i = lane; i < CDIM; i += 32) {
        float xv = xr[i];
        const float* gr = gw + (size_t)i * CE;
#pragma unroll
        for (int e = 0; e < CE; e++) acc[e] += xv * gr[e];
    }
#pragma unroll
    for (int e = 0; e < CE; e++) {
#pragma unroll
        for (int o = 16; o > 0; o >>= 1)
            acc[e] += __shfl_xor_sync(0xffffffffu, acc[e], o);
    }
    if (lane == 0) {
        float l[CE];
#pragma unroll
        for (int e = 0; e < CE; e++) l[e] = acc[e] + gb[e];
        bool used[CE];
#pragma unroll
        for (int e = 0; e < CE; e++) used[e] = false;
        int sel[CTOPK];
        float m = -3.4e38f;
        for (int k = 0; k < CTOPK; k++) {          // strict >: first index wins ties
            int best = 0; float bv = -3.4e38f;
            for (int e = 0; e < CE; e++)
                if (!used[e] && l[e] > bv) { bv = l[e]; best = e; }
            used[best] = true; sel[k] = best;
            if (k == 0) m = bv;
        }
        float ex[CTOPK]; float s = 0.f;
        for (int k = 0; k < CTOPK; k++) { ex[k] = __expf(l[sel[k]] - m); s += ex[k]; }
        float inv = 1.f / s;
        float outv[CE];
#pragma unroll
        for (int e = 0; e < CE; e++) outv[e] = 0.f;
        for (int k = 0; k < CTOPK; k++) outv[sel[k]] = ex[k] * inv;
        float* gr = g + (size_t)tok * CE;
        for (int e = 0; e < CE; e++) gr[e] = outv[e];
    }
}

// ---------------- gbias = g @ bias, bias cached in smem (16 tokens/block) ---
__global__ void __launch_bounds__(256) gbias_kernel(const float* __restrict__ G,
                                                    const float* __restrict__ bias,  // [E,512]
                                                    float* __restrict__ gbias)       // [T,512]
{
    __shared__ float bs[CE*CDIM];    // 20KB
    __shared__ float gs[16*CE];
    int tid = threadIdx.x;
    for (int i = tid; i < CE*CDIM; i += 256) bs[i] = bias[i];
    for (int i = tid; i < 16*CE; i += 256) gs[i] = G[(size_t)blockIdx.x*16*CE + i];
    __syncthreads();
    int lane = tid & 31;
    int wrow = tid >> 5;    // 0..7
#pragma unroll
    for (int tt = 0; tt < 2; tt++) {
        int tr = tt*8 + wrow;
        size_t row = (size_t)blockIdx.x*16 + tr;
        float ge[CE];
#pragma unroll
        for (int e = 0; e < CE; e++) ge[e] = gs[tr*CE + e];
#pragma unroll
        for (int v = 0; v < 4; v++) {
            int c = lane*4 + v*128;
            float4 s = make_float4(0.f,0.f,0.f,0.f);
#pragma unroll
            for (int e = 0; e < CE; e++) {
                float4 b4 = *(const float4*)&bs[e*CDIM + c];
                s.x += ge[e]*b4.x; s.y += ge[e]*b4.y;
                s.z += ge[e]*b4.z; s.w += ge[e]*b4.w;
            }
            *(float4*)&gbias[row*CDIM + c] = s;
        }
    }
}

// --------- tf32 tensor-core MoE GEMM, BK=32, double-buffered, split-K -------
// C[M,512] = A'(g*x)[M,5120] @ W[5120,512] (+ GB if not split)
template<int BM, int BN, int WR, int WC, int BK>
__global__ void __launch_bounds__(WR*WC*32) moe_mma(const float* __restrict__ X,
                                                    const float* __restrict__ G,
                                                    const float* __restrict__ W,
                                                    const float* __restrict__ GB,
                                                    float* __restrict__ C,
                                                    int klen, int m_rows)
{
    constexpr int THREADS = WR * WC * 32;
    constexpr int MT = BM / WR / 16;
    constexpr int NT = BN / WC / 8;
    constexpr int KF4 = BK / 4;
    constexpr int KC  = BK / 8;
    constexpr int LA = BM * KF4 / THREADS;
    constexpr int LB = BK * (BN/4) / THREADS;
    constexpr int ASZ = KC * (BM/16) * 32 * 4;
    constexpr int BSZ = KC * (BN/8)  * 32 * 2;

    __shared__ float As[2 * ASZ];
    __shared__ float Bs[2 * BSZ];

    const int tid  = threadIdx.x;
    const int w    = tid >> 5;
    const int lane = tid & 31;
    const int wr   = w / WC;
    const int wc   = w % WC;
    const int bm   = blockIdx.y * BM;
    const int bn   = blockIdx.x * BN;
    const int kbeg = blockIdx.z * klen;
    const int kend = kbeg + klen;

    int am[LA], akk[LA], abase[LA];
#pragma unroll
    for (int l = 0; l < LA; l++) {
        int idx = tid + l * THREADS;
        am[l]  = idx / KF4;
        akk[l] = (idx % KF4) << 2;
        int k8 = akk[l] >> 3;
        int mt = am[l] >> 4;
        abase[l] = ((k8 * (BM/16) + mt) * 32 + ((am[l] & 7) << 2)) * 4
                 + ((am[l] >> 3) & 1) + 2 * ((akk[l] >> 2) & 1);
    }
    int br[LB], bn4[LB], bbase[LB];
#pragma unroll
    for (int l = 0; l < LB; l++) {
        int idx = tid + l * THREADS;
        br[l]  = idx / (BN/4);
        bn4[l] = (idx % (BN/4)) << 2;
        bbase[l] = (((br[l] >> 3) * (BN/8) + (bn4[l] >> 3)) * 32
                    + ((bn4[l] & 7) << 2) + (br[l] & 3)) * 2 + ((br[l] >> 2) & 1);
    }

    float4 pa[LA], pb[LB];
    float  ga[LA];
    auto load_tiles = [&](int k0) {
#pragma unroll
        for (int l = 0; l < LA; l++) {
            pa[l] = *(const float4*)&X[(size_t)(bm + am[l]) * CDIM + (k0 & 511) + akk[l]];
            ga[l] = G[(size_t)(bm + am[l]) * CE + (k0 >> 9)];
        }
#pragma unroll
        for (int l = 0; l < LB; l++)
            pb[l] = *(const float4*)&W[(size_t)(k0 + br[l]) * CDIM + bn + bn4[l]];
    };
    auto stage = [&](float* Ap, float* Bp) {
#pragma unroll
        for (int l = 0; l < LA; l++) {
            float g = ga[l];
            Ap[abase[l] + 0]  = __uint_as_float(f2tf32(pa[l].x * g));
            Ap[abase[l] + 4]  = __uint_as_float(f2tf32(pa[l].y * g));
            Ap[abase[l] + 8]  = __uint_as_float(f2tf32(pa[l].z * g));
            Ap[abase[l] + 12] = __uint_as_float(f2tf32(pa[l].w * g));
        }
#pragma unroll
        for (int l = 0; l < LB; l++) {
            Bp[bbase[l] + 0]  = __uint_as_float(f2tf32(pb[l].x));
            Bp[bbase[l] + 8]  = __uint_as_float(f2tf32(pb[l].y));
            Bp[bbase[l] + 16] = __uint_as_float(f2tf32(pb[l].z));
            Bp[bbase[l] + 24] = __uint_as_float(f2tf32(pb[l].w));
        }
    };

    float c[MT][NT][4] = {};

    load_tiles(kbeg);
    stage(As, Bs);
    if (kbeg + BK < kend) load_tiles(kbeg + BK);
    __syncthreads();

    for (int k0 = kbeg; k0 < kend; k0 += BK) {
        const int p = ((k0 - kbeg) / BK) & 1;
        const uint32_t* Asu = (const uint32_t*)(As + p * ASZ);
        const uint32_t* Bsu = (const uint32_t*)(Bs + p * BSZ);
        if (k0 + BK < kend) {
            stage(As + (p^1) * ASZ, Bs + (p^1) * BSZ);
            if (k0 + 2*BK < kend) load_tiles(k0 + 2*BK);
        }
#pragma unroll
        for (int k8 = 0; k8 < KC; k8++) {
            uint4 a[MT];
            uint2 b[NT];
#pragma unroll
            for (int i = 0; i < MT; i++)
                a[i] = *(const uint4*)&Asu[((k8 * (BM/16) + wr*MT + i) * 32 + lane) * 4];
#pragma unroll
            for (int j = 0; j < NT; j++)
                b[j] = *(const uint2*)&Bsu[((k8 * (BN/8) + wc*NT + j) * 32 + lane) * 2];
#pragma unroll
            for (int i = 0; i < MT; i++)
#pragma unroll
                for (int j = 0; j < NT; j++)
                    mma_tf32(c[i][j], a[i].x, a[i].y, a[i].z, a[i].w, b[j].x, b[j].y);
        }
        __syncthreads();
    }

    const bool split = (gridDim.z > 1);
    float* Co = C + (split ? (size_t)blockIdx.z * m_rows * CDIM : 0);
#pragma unroll
    for (int i = 0; i < MT; i++) {
#pragma unroll
        for (int j = 0; j < NT; j++) {
            int row = bm + wr*MT*16 + i*16 + (lane >> 2);
            int col = bn + wc*NT*8 + j*8 + ((lane & 3) << 1);
            float b00 = 0.f, b01 = 0.f, b10 = 0.f, b11 = 0.f;
            if (!split) {
                float2 b0 = *(const float2*)&GB[(size_t)row * CDIM + col];
                float2 b1 = *(const float2*)&GB[(size_t)(row + 8) * CDIM + col];
                b00 = b0.x; b01 = b0.y; b10 = b1.x; b11 = b1.y;
            }
            *(float2*)&Co[(size_t)row * CDIM + col] =
                make_float2(c[i][j][0] + b00, c[i][j][1] + b01);
            *(float2*)&Co[(size_t)(row + 8) * CDIM + col] =
                make_float2(c[i][j][2] + b10, c[i][j][3] + b11);
        }
    }
}

// ------- split-K reduce with gate-bias fold: out = Σ part + Σ_e g·bias ------
__global__ void __launch_bounds__(256) reduce_kg(const float* __restrict__ part,
                                                 const float* __restrict__ G,
                                                 const float* __restrict__ bias,  // [E,512]
                                                 float* __restrict__ out)
{
    __shared__ float bs[CE*CDIM];    // 20KB
    int tid = threadIdx.x;
    for (int i = tid; i < CE*CDIM; i += 256) bs[i] = bias[i];
    __syncthreads();
    int lane = tid & 31;
    size_t row = (size_t)blockIdx.x*8 + (tid >> 5);
    float ge[CE];
#pragma unroll
    for (int e = 0; e < CE; e++) ge[e] = G[row*CE + e];
#pragma unroll
    for (int v = 0; v < 4; v++) {
        int c = lane*4 + v*128;
        size_t i = row*CDIM + c;
        float4 s = make_float4(0.f,0.f,0.f,0.f);
#pragma unroll
        for (int z = 0; z < KSPLIT; z++) {
            float4 p = *(const float4*)&part[(size_t)z * X_ELEMS + i];
            s.x += p.x; s.y += p.y; s.z += p.z; s.w += p.w;
        }
#pragma unroll
        for (int e = 0; e < CE; e++) {
            float4 b4 = *(const float4*)&bs[e*CDIM + c];
            s.x += ge[e]*b4.x; s.y += ge[e]*b4.y;
            s.z += ge[e]*b4.z; s.w += ge[e]*b4.w;
        }
        *(float4*)&out[i] = s;
    }
}

__global__ void __launch_bounds__(256) reduce_av(const float* __restrict__ part,
                                                 float* __restrict__ out)
{
    int i = (blockIdx.x * 256 + threadIdx.x) << 2;
    float4 s = *(const float4*)&part[i];
#pragma unroll
    for (int z = 1; z < AVSPLIT; z++) {
        float4 p = *(const float4*)&part[(size_t)z * X_ELEMS + i];
        s.x += p.x; s.y += p.y; s.z += p.z; s.w += p.w;
    }
    *(float4*)&out[i] = s;
}

// ---------------- QK^T * scale via tf32 mma (64q x 128k x 64d one-shot) -----
__global__ void __launch_bounds__(256) qk_mma(const float* __restrict__ qp,
                                              const float* __restrict__ kp,
                                              float* __restrict__ attn)
{
    __shared__ float As[8 * 4  * 32 * 4];
    __shared__ float Bs[8 * 16 * 32 * 2];
    const int bh = blockIdx.z;
    const int b = bh >> 3, h = bh & 7;
    const int q0 = blockIdx.y << 6;
    const int k0 = blockIdx.x << 7;
    const int tid = threadIdx.x;
    const int w = tid >> 5, lane = tid & 31;
    const int wr = w >> 2, wc = w & 3;      // 2 x 4 warps, MT=2, NT=4

#pragma unroll
    for (int l = 0; l < 4; l++) {
        int idx = tid + l*256;
        int am = idx >> 4;
        int ak4 = (idx & 15) << 2;
        float4 v = *(const float4*)&qp[((size_t)(b*CLQ + q0 + am))*CDIM + h*CHEAD + ak4];
        int k8 = ak4 >> 3;
        int base = ((k8*4 + (am>>4))*32 + ((am&7)<<2))*4 + ((am>>3)&1) + 2*((ak4>>2)&1);
        As[base + 0]  = __uint_as_float(f2tf32(v.x * CSCALE));
        As[base + 4]  = __uint_as_float(f2tf32(v.y * CSCALE));
        As[base + 8]  = __uint_as_float(f2tf32(v.z * CSCALE));
        As[base + 12] = __uint_as_float(f2tf32(v.w * CSCALE));
    }
#pragma unroll
    for (int l = 0; l < 8; l++) {
        int idx = tid + l*256;
        int n = idx >> 4;
        int bk4 = (idx & 15) << 2;
        float4 v = *(const float4*)&kp[((size_t)(b*CLKV + k0 + n))*CDIM + h*CHEAD + bk4];
        int k8 = bk4 >> 3;
        int base = ((k8*16 + (n>>3))*32 + ((n&7)<<2))*2 + ((bk4>>2)&1);
        Bs[base + 0] = __uint_as_float(f2tf32(v.x));
        Bs[base + 2] = __uint_as_float(f2tf32(v.y));
        Bs[base + 4] = __uint_as_float(f2tf32(v.z));
        Bs[base + 6] = __uint_as_float(f2tf32(v.w));
    }
    __syncthreads();

    const uint32_t* Asu = (const uint32_t*)As;
    const uint32_t* Bsu = (const uint32_t*)Bs;
    float c[2][4][4] = {};
#pragma unroll
    for (int k8 = 0; k8 < 8; k8++) {
        uint4 a[2];
        uint2 bb[4];
#pragma unroll
        for (int i = 0; i < 2; i++)
            a[i] = *(const uint4*)&Asu[((k8*4 + wr*2 + i)*32 + lane)*4];
#pragma unroll
        for (int j = 0; j < 4; j++)
            bb[j] = *(const uint2*)&Bsu[((k8*16 + wc*4 + j)*32 + lane)*2];
#pragma unroll
        for (int i = 0; i < 2; i++)
#pragma unroll
            for (int j = 0; j < 4; j++)
                mma_tf32(c[i][j], a[i].x, a[i].y, a[i].z, a[i].w, bb[j].x, bb[j].y);
    }
#pragma unroll
    for (int i = 0; i < 2; i++) {
#pragma unroll
        for (int j = 0; j < 4; j++) {
            int row = q0 + wr*32 + i*16 + (lane >> 2);
            int col = k0 + wc*32 + j*8 + ((lane & 3) << 1);
            *(float2*)&attn[((size_t)(bh*CLQ + row))*CLKV + col] =
                make_float2(c[i][j][0], c[i][j][1]);
            *(float2*)&attn[((size_t)(bh*CLQ + row + 8))*CLKV + col] =
                make_float2(c[i][j][2], c[i][j][3]);
        }
    }
}

// ---------------- row softmax over 4096, in place ---------------------------
__global__ void __launch_bounds__(256) softmax_kernel(float* __restrict__ attn)
{
    __shared__ float red[32];
    size_t row = (size_t)blockIdx.x * CLKV;
    int tid = threadIdx.x;
    float v[16];
    float m = -3.4e38f;
#pragma unroll
    for (int l = 0; l < 4; l++) {
        float4 x4 = *(const float4*)&attn[row + tid*4 + l*1024];
        v[l*4+0]=x4.x; v[l*4+1]=x4.y; v[l*4+2]=x4.z; v[l*4+3]=x4.w;
    }
#pragma unroll
    for (int i = 0; i < 16; i++) m = fmaxf(m, v[i]);
#pragma unroll
    for (int o = 16; o > 0; o >>= 1) m = fmaxf(m, __shfl_xor_sync(~0u, m, o));
    if ((tid & 31) == 0) red[tid >> 5] = m;
    __syncthreads();
    if (tid < 32) {
        float t = (tid < 8) ? red[tid] : -3.4e38f;
#pragma unroll
        for (int o = 4; o > 0; o >>= 1) t = fmaxf(t, __shfl_xor_sync(~0u, t, o));
        if (tid == 0) red[0] = t;
    }
    __syncthreads();
    m = red[0];
    float s = 0.f;
#pragma unroll
    for (int i = 0; i < 16; i++) { v[i] = __expf(v[i] - m); s += v[i]; }
#pragma unroll
    for (int o = 16; o > 0; o >>= 1) s += __shfl_xor_sync(~0u, s, o);
    __syncthreads();
    if ((tid & 31) == 0) red[tid >> 5] = s;
    __syncthreads();
    if (tid == 0) {
        float t = 0.f;
        for (int i = 0; i < 8; i++) t += red[i];
        red[0] = 1.f / t;
    }
    __syncthreads();
    float inv = red[0];
#pragma unroll
    for (int l = 0; l < 4; l++) {
        *(float4*)&attn[row + tid*4 + l*1024] =
            make_float4(v[l*4]*inv, v[l*4+1]*inv, v[l*4+2]*inv, v[l*4+3]*inv);
    }
}

// ---------------- P @ V via tf32 mma, split-K over KV, double-buffered ------
__global__ void __launch_bounds__(256) av_mma(const float* __restrict__ attn,
                                              const float* __restrict__ vp,
                                              float* __restrict__ part)
{
    constexpr int ASZ = 4 * 4 * 32 * 4;   // 2048 floats per stage
    constexpr int BSZ = 4 * 8 * 32 * 2;   // 2048 floats per stage
    __shared__ float As[2 * ASZ];
    __shared__ float Bs[2 * BSZ];
    const int bh = blockIdx.y;
    const int b = bh >> 3, h = bh & 7;
    const int q0 = blockIdx.x << 6;
    const int kbeg = blockIdx.z * (CLKV / AVSPLIT);
    const int kend = kbeg + (CLKV / AVSPLIT);
    const int tid = threadIdx.x;
    const int w = tid >> 5, lane = tid & 31;
    const int wr = w >> 1, wc = w & 1;     // 4 x 2 warps, MT=1, NT=4

    int am[2], ak4[2], abase[2];
#pragma unroll
    for (int l = 0; l < 2; l++) {
        int idx = tid + l*256;
        am[l]  = idx >> 3;
        ak4[l] = (idx & 7) << 2;
        int k8 = ak4[l] >> 3;
        abase[l] = ((k8*4 + (am[l]>>4))*32 + ((am[l]&7)<<2))*4
                 + ((am[l]>>3)&1) + 2*((ak4[l]>>2)&1);
    }
    int br[2], bn4[2], bbase[2];
#pragma unroll
    for (int l = 0; l < 2; l++) {
        int idx = tid + l*256;
        br[l]  = idx >> 4;
        bn4[l] = (idx & 15) << 2;
        bbase[l] = (((br[l]>>3)*8 + (bn4[l]>>3))*32
                    + ((bn4[l]&7)<<2) + (br[l]&3))*2 + ((br[l]>>2)&1);
    }

    float4 pa[2], pb[2];
    auto load_tiles = [&](int k0) {
#pragma unroll
        for (int l = 0; l < 2; l++)
            pa[l] = *(const float4*)&attn[((size_t)(bh*CLQ + q0 + am[l]))*CLKV + k0 + ak4[l]];
#pragma unroll
        for (int l = 0; l < 2; l++)
            pb[l] = *(const float4*)&vp[((size_t)(b*CLKV + k0 + br[l]))*CDIM + h*CHEAD + bn4[l]];
    };
    auto stage = [&](float* Ap, float* Bp) {
#pragma unroll
        for (int l = 0; l < 2; l++) {
            Ap[abase[l] + 0]  = __uint_as_float(f2tf32(pa[l].x));
            Ap[abase[l] + 4]  = __uint_as_float(f2tf32(pa[l].y));
            Ap[abase[l] + 8]  = __uint_as_float(f2tf32(pa[l].z));
            Ap[abase[l] + 12] = __uint_as_float(f2tf32(pa[l].w));
        }
#pragma unroll
        for (int l = 0; l < 2; l++) {
            Bp[bbase[l] + 0]  = __uint_as_float(f2tf32(pb[l].x));
            Bp[bbase[l] + 8]  = __uint_as_float(f2tf32(pb[l].y));
            Bp[bbase[l] + 16] = __uint_as_float(f2tf32(pb[l].z));
            Bp[bbase[l] + 24] = __uint_as_float(f2tf32(pb[l].w));
        }
    };

    float c[4][4] = {};

    load_tiles(kbeg);
    stage(As, Bs);
    if (kbeg + 32 < kend) load_tiles(kbeg + 32);
    __syncthreads();

    for (int k0 = kbeg; k0 < kend; k0 += 32) {
        const int p = ((k0 - kbeg) >> 5) & 1;
        const uint32_t* Asu = (const uint32_t*)(As + p * ASZ);
        const uint32_t* Bsu = (const uint32_t*)(Bs + p * BSZ);
        if (k0 + 32 < kend) {
            stage(As + (p^1)*ASZ, Bs + (p^1)*BSZ);
            if (k0 + 64 < kend) load_tiles(k0 + 64);
        }
#pragma unroll
        for (int k8 = 0; k8 < 4; k8++) {
            uint4 a = *(const uint4*)&Asu[((k8*4 + wr)*32 + lane)*4];
            uint2 bb[4];
#pragma unroll
            for (int j = 0; j < 4; j++)
                bb[j] = *(const uint2*)&Bsu[((k8*8 + wc*4 + j)*32 + lane)*2];
#pragma unroll
            for (int j = 0; j < 4; j++)
                mma_tf32(c[j], a.x, a.y, a.z, a.w, bb[j].x, bb[j].y);
        }
        __syncthreads();
    }
    float* Co = part + (size_t)blockIdx.z * X_ELEMS;
#pragma unroll
    for (int j = 0; j < 4; j++) {
        int row = q0 + wr*16 + (lane >> 2);
        int col = h*CHEAD + wc*32 + j*8 + ((lane & 3) << 1);
        *(float2*)&Co[((size_t)(b*CLQ + row))*CDIM + col] =
            make_float2(c[j][0], c[j][1]);
        *(float2*)&Co[((size_t)(b*CLQ + row + 8))*CDIM + col] =
            make_float2(c[j][2], c[j][3]);
    }
}

// ---------------- launch ----------------------------------------------------
extern "C" void kernel_launch(void* const* d_in, const int* in_sizes, int n_in,
                              void* d_out, int out_size)
{
    const float* q    = (const float*)d_in[0];
    const float* kv   = (const float*)d_in[1];
    const float* q_gw = (const float*)d_in[2];
    const float* q_gb = (const float*)d_in[3];
    const float* q_w  = (const float*)d_in[4];
    const float* q_b  = (const float*)d_in[5];
    const float* k_gw = (const float*)d_in[6];
    const float* k_gb = (const float*)d_in[7];
    const float* k_w  = (const float*)d_in[8];
    const float* k_b  = (const float*)d_in[9];
    const float* v_gw = (const float*)d_in[10];
    const float* v_gb = (const float*)d_in[11];
    const float* v_w  = (const float*)d_in[12];
    const float* v_b  = (const float*)d_in[13];
    const float* o_gw = (const float*)d_in[14];
    const float* o_gb = (const float*)d_in[15];
    const float* o_w  = (const float*)d_in[16];
    const float* o_b  = (const float*)d_in[17];
    float* out = (float*)d_out;

    static float *qp=nullptr,*kp=nullptr,*vp=nullptr,*xbuf=nullptr;
    static float *gq=nullptr,*gk=nullptr,*gv=nullptr,*go=nullptr,*afb=nullptr;
    static float *gbk=nullptr,*gbv=nullptr,*part=nullptr;
    if (!qp) {
        cudaGetSymbolAddress((void**)&qp,   g_qp);
        cudaGetSymbolAddress((void**)&kp,   g_kp);
        cudaGetSymbolAddress((void**)&vp,   g_vp);
        cudaGetSymbolAddress((void**)&xbuf, g_xbuf);
        cudaGetSymbolAddress((void**)&gq,   g_gq);
        cudaGetSymbolAddress((void**)&gk,   g_gk);
        cudaGetSymbolAddress((void**)&gv,   g_gv);
        cudaGetSymbolAddress((void**)&go,   g_go);
        cudaGetSymbolAddress((void**)&afb,  g_attn_fb);
        cudaGetSymbolAddress((void**)&gbk,  g_gbk);
        cudaGetSymbolAddress((void**)&gbv,  g_gbv);
        cudaGetSymbolAddress((void**)&part, g_part);
    }
    // output layout: x (524288 floats) then attn (33554432 floats)
    float* attn = (out_size >= (X_ELEMS + ATTN_ELEMS)) ? (out + X_ELEMS) : afb;

    gate_kernel<<<CTQ/8, 256>>>(q,  q_gw, q_gb, gq, CTQ);
    gate_kernel<<<CTKV/8, 256>>>(kv, k_gw, k_gb, gk, CTKV);
    gate_kernel<<<CTKV/8, 256>>>(kv, v_gw, v_gb, gv, CTKV);
    gbias_kernel<<<CTKV/16, 256>>>(gk, k_b, gbk);
    gbias_kernel<<<CTKV/16, 256>>>(gv, v_b, gbv);

    // Q projection: split-K over 8 slices of 640, reduce folds gate-bias
    moe_mma<64,64,2,2,32><<<dim3(CDIM/64, CTQ/64, KSPLIT), 128>>>(q, gq, q_w, nullptr, part, CK/KSPLIT, CTQ);
    reduce_kg<<<CTQ/8, 256>>>(part, gq, q_b, qp);

    // K/V projections: 128x64 tiles -> 512 CTAs each
    moe_mma<128,64,4,2,32><<<dim3(CDIM/64, CTKV/128, 1), 256>>>(kv, gk, k_w, gbk, kp, CK, CTKV);
    moe_mma<128,64,4,2,32><<<dim3(CDIM/64, CTKV/128, 1), 256>>>(kv, gv, v_w, gbv, vp, CK, CTKV);

    qk_mma<<<dim3(CLKV/128, CLQ/64, CB*CH), 256>>>(qp, kp, attn);
    softmax_kernel<<<CB*CH*CLQ, 256>>>(attn);

    av_mma<<<dim3(CLQ/64, CB*CH, AVSPLIT), 256>>>(attn, vp, part);
    reduce_av<<<X_ELEMS/1024, 256>>>(part, xbuf);

    gate_kernel<<<CTQ/8, 256>>>(xbuf, o_gw, o_gb, go, CTQ);

    moe_mma<64,64,2,2,32><<<dim3(CDIM/64, CTQ/64, KSPLIT), 128>>>(xbuf, go, o_w, nullptr, part, CK/KSPLIT, CTQ);
    reduce_kg<<<CTQ/8, 256>>>(part, go, o_b, out);
}

// round 12
// speedup vs baseline: 1.9068x; 1.1647x over previous
#include <cuda_runtime.h>
#include <math.h>
#include <stdint.h>

#define CB 2
#define CLQ 512
#define CLKV 4096
#define CDIM 512
#define CH 8
#define CE 10
#define CTOPK 5
#define CHEAD 64
#define CTQ (CB*CLQ)      /* 1024 */
#define CTKV (CB*CLKV)    /* 8192 */
#define CK (CE*CDIM)      /* 5120 */
#define CSCALE 0.125f
#define X_ELEMS (CTQ*CDIM)              /* 524288 */
#define ATTN_ELEMS (CB*CH*CLQ*CLKV)     /* 33554432 */
#define KSPLIT 8
#define AVSPLIT 8
#define NROWS (CB*CH*CLQ)               /* 8192 attn rows */
#define NTILE (CLKV/128)                /* 32 k-tiles per row */

// ---------------- scratch (static device globals) ---------------------------
__device__ float g_qp[CTQ*CDIM];
__device__ float g_kp[CTKV*CDIM];
__device__ float g_vp[CTKV*CDIM];
__device__ float g_xbuf[CTQ*CDIM];
__device__ float g_gq[CTQ*CE];
__device__ float g_gk[CTKV*CE];
__device__ float g_gv[CTKV*CE];
__device__ float g_go[CTQ*CE];
__device__ float g_gbk[CTKV*CDIM];
__device__ float g_gbv[CTKV*CDIM];
__device__ float g_part[KSPLIT*CTQ*CDIM];
__device__ float g_mrow[NROWS*NTILE];
__device__ float g_srow[NROWS*NTILE];
__device__ float g_frow[NROWS*NTILE];
__device__ float g_attn_fb[ATTN_ELEMS];

// ---------------- helpers ---------------------------------------------------
__device__ __forceinline__ uint32_t f2tf32(float x) {
    uint32_t u;
    asm("cvt.rna.tf32.f32 %0, %1;" : "=r"(u) : "f"(x));
    return u;
}

__device__ __forceinline__ void mma_tf32(float c[4],
                                         uint32_t a0, uint32_t a1, uint32_t a2, uint32_t a3,
                                         uint32_t b0, uint32_t b1) {
    asm volatile(
        "mma.sync.aligned.m16n8k8.row.col.f32.tf32.tf32.f32 "
        "{%0,%1,%2,%3}, {%4,%5,%6,%7}, {%8,%9}, {%0,%1,%2,%3};"
        : "+f"(c[0]), "+f"(c[1]), "+f"(c[2]), "+f"(c[3])
        : "r"(a0), "r"(a1), "r"(a2), "r"(a3), "r"(b0), "r"(b1));
}

// ---------------- gate: softmax -> top-5 -> renormalize (warp/token) --------
__global__ void gate_kernel(const float* __restrict__ x,
                            const float* __restrict__ gw,   // [512, E]
                            const float* __restrict__ gb,   // [E]
                            float* __restrict__ g,          // [T, E]
                            int T)
{
    int tok  = (blockIdx.x * blockDim.x + threadIdx.x) >> 5;
    int lane = threadIdx.x & 31;
    if (tok >= T) return;
    const float* xr = x + (size_t)tok * CDIM;
    float acc[CE];
#pragma unroll
    for (int e = 0; e < CE; e++) acc[e] = 0.f;
    for (int i = lane; i < CDIM; i += 32) {
        float xv = xr[i];
        const float* gr = gw + (size_t)i * CE;
#pragma unroll
        for (int e = 0; e < CE; e++) acc[e] += xv * gr[e];
    }
#pragma unroll
    for (int e = 0; e < CE; e++) {
#pragma unroll
        for (int o = 16; o > 0; o >>= 1)
            acc[e] += __shfl_xor_sync(0xffffffffu, acc[e], o);
    }
    if (lane == 0) {
        float l[CE];
#pragma unroll
        for (int e = 0; e < CE; e++) l[e] = acc[e] + gb[e];
        bool used[CE];
#pragma unroll
        for (int e = 0; e < CE; e++) used[e] = false;
        int sel[CTOPK];
        float m = -3.4e38f;
        for (int k = 0; k < CTOPK; k++) {          // strict >: first index wins ties
            int best = 0; float bv = -3.4e38f;
            for (int e = 0; e < CE; e++)
                if (!used[e] && l[e] > bv) { bv = l[e]; best = e; }
            used[best] = true; sel[k] = best;
            if (k == 0) m = bv;
        }
        float ex[CTOPK]; float s = 0.f;
        for (int k = 0; k < CTOPK; k++) { ex[k] = __expf(l[sel[k]] - m); s += ex[k]; }
        float inv = 1.f / s;
        float outv[CE];
#pragma unroll
        for (int e = 0; e < CE; e++) outv[e] = 0.f;
        for (int k = 0; k < CTOPK; k++) outv[sel[k]] = ex[k] * inv;
        float* gr = g + (size_t)tok * CE;
        for (int e = 0; e < CE; e++) gr[e] = outv[e];
    }
}

// ---------------- gbias = g @ bias, bias cached in smem (16 tokens/block) ---
__global__ void __launch_bounds__(256) gbias_kernel(const float* __restrict__ G,
                                                    const float* __restrict__ bias,  // [E,512]
                                                    float* __restrict__ gbias)       // [T,512]
{
    __shared__ float bs[CE*CDIM];    // 20KB
    __shared__ float gs[16*CE];
    int tid = threadIdx.x;
    for (int i = tid; i < CE*CDIM; i += 256) bs[i] = bias[i];
    for (int i = tid; i < 16*CE; i += 256) gs[i] = G[(size_t)blockIdx.x*16*CE + i];
    __syncthreads();
    int lane = tid & 31;
    int wrow = tid >> 5;    // 0..7
#pragma unroll
    for (int tt = 0; tt < 2; tt++) {
        int tr = tt*8 + wrow;
        size_t row = (size_t)blockIdx.x*16 + tr;
        float ge[CE];
#pragma unroll
        for (int e = 0; e < CE; e++) ge[e] = gs[tr*CE + e];
#pragma unroll
        for (int v = 0; v < 4; v++) {
            int c = lane*4 + v*128;
            float4 s = make_float4(0.f,0.f,0.f,0.f);
#pragma unroll
            for (int e = 0; e < CE; e++) {
                float4 b4 = *(const float4*)&bs[e*CDIM + c];
                s.x += ge[e]*b4.x; s.y += ge[e]*b4.y;
                s.z += ge[e]*b4.z; s.w += ge[e]*b4.w;
            }
            *(float4*)&gbias[row*CDIM + c] = s;
        }
    }
}

// --------- tf32 tensor-core MoE GEMM, BK=32, double-buffered, split-K -------
template<int BM, int BN, int WR, int WC, int BK>
__global__ void __launch_bounds__(WR*WC*32) moe_mma(const float* __restrict__ X,
                                                    const float* __restrict__ G,
                                                    const float* __restrict__ W,
                                                    const float* __restrict__ GB,
                                                    float* __restrict__ C,
                                                    int klen, int m_rows)
{
    constexpr int THREADS = WR * WC * 32;
    constexpr int MT = BM / WR / 16;
    constexpr int NT = BN / WC / 8;
    constexpr int KF4 = BK / 4;
    constexpr int KC  = BK / 8;
    constexpr int LA = BM * KF4 / THREADS;
    constexpr int LB = BK * (BN/4) / THREADS;
    constexpr int ASZ = KC * (BM/16) * 32 * 4;
    constexpr int BSZ = KC * (BN/8)  * 32 * 2;

    __shared__ float As[2 * ASZ];
    __shared__ float Bs[2 * BSZ];

    const int tid  = threadIdx.x;
    const int w    = tid >> 5;
    const int lane = tid & 31;
    const int wr   = w / WC;
    const int wc   = w % WC;
    const int bm   = blockIdx.y * BM;
    const int bn   = blockIdx.x * BN;
    const int kbeg = blockIdx.z * klen;
    const int kend = kbeg + klen;

    int am[LA], akk[LA], abase[LA];
#pragma unroll
    for (int l = 0; l < LA; l++) {
        int idx = tid + l * THREADS;
        am[l]  = idx / KF4;
        akk[l] = (idx % KF4) << 2;
        int k8 = akk[l] >> 3;
        int mt = am[l] >> 4;
        abase[l] = ((k8 * (BM/16) + mt) * 32 + ((am[l] & 7) << 2)) * 4
                 + ((am[l] >> 3) & 1) + 2 * ((akk[l] >> 2) & 1);
    }
    int br[LB], bn4[LB], bbase[LB];
#pragma unroll
    for (int l = 0; l < LB; l++) {
        int idx = tid + l * THREADS;
        br[l]  = idx / (BN/4);
        bn4[l] = (idx % (BN/4)) << 2;
        bbase[l] = (((br[l] >> 3) * (BN/8) + (bn4[l] >> 3)) * 32
                    + ((bn4[l] & 7) << 2) + (br[l] & 3)) * 2 + ((br[l] >> 2) & 1);
    }

    float4 pa[LA], pb[LB];
    float  ga[LA];
    auto load_tiles = [&](int k0) {
#pragma unroll
        for (int l = 0; l < LA; l++) {
            pa[l] = *(const float4*)&X[(size_t)(bm + am[l]) * CDIM + (k0 & 511) + akk[l]];
            ga[l] = G[(size_t)(bm + am[l]) * CE + (k0 >> 9)];
        }
#pragma unroll
        for (int l = 0; l < LB; l++)
            pb[l] = *(const float4*)&W[(size_t)(k0 + br[l]) * CDIM + bn + bn4[l]];
    };
    auto stage = [&](float* Ap, float* Bp) {
#pragma unroll
        for (int l = 0; l < LA; l++) {
            float g = ga[l];
            Ap[abase[l] + 0]  = __uint_as_float(f2tf32(pa[l].x * g));
            Ap[abase[l] + 4]  = __uint_as_float(f2tf32(pa[l].y * g));
            Ap[abase[l] + 8]  = __uint_as_float(f2tf32(pa[l].z * g));
            Ap[abase[l] + 12] = __uint_as_float(f2tf32(pa[l].w * g));
        }
#pragma unroll
        for (int l = 0; l < LB; l++) {
            Bp[bbase[l] + 0]  = __uint_as_float(f2tf32(pb[l].x));
            Bp[bbase[l] + 8]  = __uint_as_float(f2tf32(pb[l].y));
            Bp[bbase[l] + 16] = __uint_as_float(f2tf32(pb[l].z));
            Bp[bbase[l] + 24] = __uint_as_float(f2tf32(pb[l].w));
        }
    };

    float c[MT][NT][4] = {};

    load_tiles(kbeg);
    stage(As, Bs);
    if (kbeg + BK < kend) load_tiles(kbeg + BK);
    __syncthreads();

    for (int k0 = kbeg; k0 < kend; k0 += BK) {
        const int p = ((k0 - kbeg) / BK) & 1;
        const uint32_t* Asu = (const uint32_t*)(As + p * ASZ);
        const uint32_t* Bsu = (const uint32_t*)(Bs + p * BSZ);
        if (k0 + BK < kend) {
            stage(As + (p^1) * ASZ, Bs + (p^1) * BSZ);
            if (k0 + 2*BK < kend) load_tiles(k0 + 2*BK);
        }
#pragma unroll
        for (int k8 = 0; k8 < KC; k8++) {
            uint4 a[MT];
            uint2 b[NT];
#pragma unroll
            for (int i = 0; i < MT; i++)
                a[i] = *(const uint4*)&Asu[((k8 * (BM/16) + wr*MT + i) * 32 + lane) * 4];
#pragma unroll
            for (int j = 0; j < NT; j++)
                b[j] = *(const uint2*)&Bsu[((k8 * (BN/8) + wc*NT + j) * 32 + lane) * 2];
#pragma unroll
            for (int i = 0; i < MT; i++)
#pragma unroll
                for (int j = 0; j < NT; j++)
                    mma_tf32(c[i][j], a[i].x, a[i].y, a[i].z, a[i].w, b[j].x, b[j].y);
        }
        __syncthreads();
    }

    const bool split = (gridDim.z > 1);
    float* Co = C + (split ? (size_t)blockIdx.z * m_rows * CDIM : 0);
#pragma unroll
    for (int i = 0; i < MT; i++) {
#pragma unroll
        for (int j = 0; j < NT; j++) {
            int row = bm + wr*MT*16 + i*16 + (lane >> 2);
            int col = bn + wc*NT*8 + j*8 + ((lane & 3) << 1);
            float b00 = 0.f, b01 = 0.f, b10 = 0.f, b11 = 0.f;
            if (!split) {
                float2 b0 = *(const float2*)&GB[(size_t)row * CDIM + col];
                float2 b1 = *(const float2*)&GB[(size_t)(row + 8) * CDIM + col];
                b00 = b0.x; b01 = b0.y; b10 = b1.x; b11 = b1.y;
            }
            *(float2*)&Co[(size_t)row * CDIM + col] =
                make_float2(c[i][j][0] + b00, c[i][j][1] + b01);
            *(float2*)&Co[(size_t)(row + 8) * CDIM + col] =
                make_float2(c[i][j][2] + b10, c[i][j][3] + b11);
        }
    }
}

// ------- split-K reduce with gate-bias fold: out = Σ part + Σ_e g·bias ------
__global__ void __launch_bounds__(256) reduce_kg(const float* __restrict__ part,
                                                 const float* __restrict__ G,
                                                 const float* __restrict__ bias,  // [E,512]
                                                 float* __restrict__ out)
{
    __shared__ float bs[CE*CDIM];    // 20KB
    int tid = threadIdx.x;
    for (int i = tid; i < CE*CDIM; i += 256) bs[i] = bias[i];
    __syncthreads();
    int lane = tid & 31;
    size_t row = (size_t)blockIdx.x*8 + (tid >> 5);
    float ge[CE];
#pragma unroll
    for (int e = 0; e < CE; e++) ge[e] = G[row*CE + e];
#pragma unroll
    for (int v = 0; v < 4; v++) {
        int c = lane*4 + v*128;
        size_t i = row*CDIM + c;
        float4 s = make_float4(0.f,0.f,0.f,0.f);
#pragma unroll
        for (int z = 0; z < KSPLIT; z++) {
            float4 p = *(const float4*)&part[(size_t)z * X_ELEMS + i];
            s.x += p.x; s.y += p.y; s.z += p.z; s.w += p.w;
        }
#pragma unroll
        for (int e = 0; e < CE; e++) {
            float4 b4 = *(const float4*)&bs[e*CDIM + c];
            s.x += ge[e]*b4.x; s.y += ge[e]*b4.y;
            s.z += ge[e]*b4.z; s.w += ge[e]*b4.w;
        }
        *(float4*)&out[i] = s;
    }
}

__global__ void __launch_bounds__(256) reduce_av(const float* __restrict__ part,
                                                 float* __restrict__ out)
{
    int i = (blockIdx.x * 256 + threadIdx.x) << 2;
    float4 s = *(const float4*)&part[i];
#pragma unroll
    for (int z = 1; z < AVSPLIT; z++) {
        float4 p = *(const float4*)&part[(size_t)z * X_ELEMS + i];
        s.x += p.x; s.y += p.y; s.z += p.z; s.w += p.w;
    }
    *(float4*)&out[i] = s;
}

// ---- QK^T*scale + tile softmax stats; writes P~=exp(l - m_tile) to attn ----
__global__ void __launch_bounds__(256) qk_mma(const float* __restrict__ qp,
                                              const float* __restrict__ kp,
                                              float* __restrict__ attn,
                                              float* __restrict__ mrow,
                                              float* __restrict__ srow)
{
    __shared__ float As[8 * 4  * 32 * 4];
    __shared__ float Bs[8 * 16 * 32 * 2];
    __shared__ float sred[4*64];
    const int bh = blockIdx.z;
    const int b = bh >> 3, h = bh & 7;
    const int q0 = blockIdx.y << 6;
    const int k0 = blockIdx.x << 7;
    const int tid = threadIdx.x;
    const int w = tid >> 5, lane = tid & 31;
    const int wr = w >> 2, wc = w & 3;      // 2 x 4 warps, MT=2, NT=4

#pragma unroll
    for (int l = 0; l < 4; l++) {
        int idx = tid + l*256;
        int am = idx >> 4;
        int ak4 = (idx & 15) << 2;
        float4 v = *(const float4*)&qp[((size_t)(b*CLQ + q0 + am))*CDIM + h*CHEAD + ak4];
        int k8 = ak4 >> 3;
        int base = ((k8*4 + (am>>4))*32 + ((am&7)<<2))*4 + ((am>>3)&1) + 2*((ak4>>2)&1);
        As[base + 0]  = __uint_as_float(f2tf32(v.x * CSCALE));
        As[base + 4]  = __uint_as_float(f2tf32(v.y * CSCALE));
        As[base + 8]  = __uint_as_float(f2tf32(v.z * CSCALE));
        As[base + 12] = __uint_as_float(f2tf32(v.w * CSCALE));
    }
#pragma unroll
    for (int l = 0; l < 8; l++) {
        int idx = tid + l*256;
        int n = idx >> 4;
        int bk4 = (idx & 15) << 2;
        float4 v = *(const float4*)&kp[((size_t)(b*CLKV + k0 + n))*CDIM + h*CHEAD + bk4];
        int k8 = bk4 >> 3;
        int base = ((k8*16 + (n>>3))*32 + ((n&7)<<2))*2 + ((bk4>>2)&1);
        Bs[base + 0] = __uint_as_float(f2tf32(v.x));
        Bs[base + 2] = __uint_as_float(f2tf32(v.y));
        Bs[base + 4] = __uint_as_float(f2tf32(v.z));
        Bs[base + 6] = __uint_as_float(f2tf32(v.w));
    }
    __syncthreads();

    const uint32_t* Asu = (const uint32_t*)As;
    const uint32_t* Bsu = (const uint32_t*)Bs;
    float c[2][4][4] = {};
#pragma unroll
    for (int k8 = 0; k8 < 8; k8++) {
        uint4 a[2];
        uint2 bb[4];
#pragma unroll
        for (int i = 0; i < 2; i++)
            a[i] = *(const uint4*)&Asu[((k8*4 + wr*2 + i)*32 + lane)*4];
#pragma unroll
        for (int j = 0; j < 4; j++)
            bb[j] = *(const uint2*)&Bsu[((k8*16 + wc*4 + j)*32 + lane)*2];
#pragma unroll
        for (int i = 0; i < 2; i++)
#pragma unroll
            for (int j = 0; j < 4; j++)
                mma_tf32(c[i][j], a[i].x, a[i].y, a[i].z, a[i].w, bb[j].x, bb[j].y);
    }

    // --- per-row tile max across the 128-k tile ---
    float tmax[2][2];
#pragma unroll
    for (int i = 0; i < 2; i++)
#pragma unroll
        for (int hh = 0; hh < 2; hh++) {
            float m = -3.4e38f;
#pragma unroll
            for (int j = 0; j < 4; j++) {
                m = fmaxf(m, c[i][j][2*hh+0]);
                m = fmaxf(m, c[i][j][2*hh+1]);
            }
#pragma unroll
            for (int o = 1; o <= 2; o <<= 1)
                m = fmaxf(m, __shfl_xor_sync(~0u, m, o));
            tmax[i][hh] = m;
        }
    if ((lane & 3) == 0) {
#pragma unroll
        for (int i = 0; i < 2; i++)
#pragma unroll
            for (int hh = 0; hh < 2; hh++) {
                int lr = wr*32 + i*16 + hh*8 + (lane >> 2);
                sred[wc*64 + lr] = tmax[i][hh];
            }
    }
    __syncthreads();
    float rmax[2][2];
#pragma unroll
    for (int i = 0; i < 2; i++)
#pragma unroll
        for (int hh = 0; hh < 2; hh++) {
            int lr = wr*32 + i*16 + hh*8 + (lane >> 2);
            float m = fmaxf(fmaxf(sred[lr], sred[64+lr]),
                            fmaxf(sred[128+lr], sred[192+lr]));
            rmax[i][hh] = m;
        }
    __syncthreads();
    // --- exponentiate in place + per-row tile sum ---
    float tsum[2][2] = {};
#pragma unroll
    for (int i = 0; i < 2; i++)
#pragma unroll
        for (int j = 0; j < 4; j++)
#pragma unroll
            for (int hh = 0; hh < 2; hh++) {
                float e0 = __expf(c[i][j][2*hh+0] - rmax[i][hh]);
                float e1 = __expf(c[i][j][2*hh+1] - rmax[i][hh]);
                c[i][j][2*hh+0] = e0;
                c[i][j][2*hh+1] = e1;
                tsum[i][hh] += e0 + e1;
            }
#pragma unroll
    for (int i = 0; i < 2; i++)
#pragma unroll
        for (int hh = 0; hh < 2; hh++)
#pragma unroll
            for (int o = 1; o <= 2; o <<= 1)
                tsum[i][hh] += __shfl_xor_sync(~0u, tsum[i][hh], o);
    if ((lane & 3) == 0) {
#pragma unroll
        for (int i = 0; i < 2; i++)
#pragma unroll
            for (int hh = 0; hh < 2; hh++) {
                int lr = wr*32 + i*16 + hh*8 + (lane >> 2);
                sred[wc*64 + lr] = tsum[i][hh];
            }
    }
    __syncthreads();
    if (wc == 0 && (lane & 3) == 0) {
#pragma unroll
        for (int i = 0; i < 2; i++)
#pragma unroll
            for (int hh = 0; hh < 2; hh++) {
                int lr = wr*32 + i*16 + hh*8 + (lane >> 2);
                float s = sred[lr] + sred[64+lr] + sred[128+lr] + sred[192+lr];
                size_t ridx = ((size_t)bh*CLQ + q0 + lr)*NTILE + blockIdx.x;
                mrow[ridx] = rmax[i][hh];
                srow[ridx] = s;
            }
    }

    // --- store P~ ---
#pragma unroll
    for (int i = 0; i < 2; i++) {
#pragma unroll
        for (int j = 0; j < 4; j++) {
            int row = q0 + wr*32 + i*16 + (lane >> 2);
            int col = k0 + wc*32 + j*8 + ((lane & 3) << 1);
            *(float2*)&attn[((size_t)(bh*CLQ + row))*CLKV + col] =
                make_float2(c[i][j][0], c[i][j][1]);
            *(float2*)&attn[((size_t)(bh*CLQ + row + 8))*CLKV + col] =
                make_float2(c[i][j][2], c[i][j][3]);
        }
    }
}

// ---- combine tile stats -> per-(row,tile) rescale factor f = exp(m_t-m)/S --
__global__ void __launch_bounds__(256) sm_combine(const float* __restrict__ mrow,
                                                  const float* __restrict__ srow,
                                                  float* __restrict__ frow)
{
    size_t row = (size_t)blockIdx.x*8 + (threadIdx.x >> 5);
    int t = threadIdx.x & 31;
    float m = mrow[row*NTILE + t];
    float s = srow[row*NTILE + t];
    float gm = m;
#pragma unroll
    for (int o = 16; o > 0; o >>= 1) gm = fmaxf(gm, __shfl_xor_sync(~0u, gm, o));
    float e = __expf(m - gm);
    float ws = s * e;
#pragma unroll
    for (int o = 16; o > 0; o >>= 1) ws += __shfl_xor_sync(~0u, ws, o);
    frow[row*NTILE + t] = e / ws;
}

// ---- P @ V: rescale P~ -> final attn (written back) + mma, split-K over KV -
__global__ void __launch_bounds__(256) av_mma(float* __restrict__ attn,
                                              const float* __restrict__ vp,
                                              const float* __restrict__ frow,
                                              float* __restrict__ part)
{
    constexpr int ASZ = 4 * 4 * 32 * 4;
    constexpr int BSZ = 4 * 8 * 32 * 2;
    __shared__ float As[2 * ASZ];
    __shared__ float Bs[2 * BSZ];
    const int bh = blockIdx.y;
    const int b = bh >> 3, h = bh & 7;
    const int q0 = blockIdx.x << 6;
    const int kbeg = blockIdx.z * (CLKV / AVSPLIT);
    const int kend = kbeg + (CLKV / AVSPLIT);
    const int tid = threadIdx.x;
    const int w = tid >> 5, lane = tid & 31;
    const int wr = w >> 1, wc = w & 1;     // 4 x 2 warps, MT=1, NT=4

    int am[2], ak4[2], abase[2];
#pragma unroll
    for (int l = 0; l < 2; l++) {
        int idx = tid + l*256;
        am[l]  = idx >> 3;
        ak4[l] = (idx & 7) << 2;
        int k8 = ak4[l] >> 3;
        abase[l] = ((k8*4 + (am[l]>>4))*32 + ((am[l]&7)<<2))*4
                 + ((am[l]>>3)&1) + 2*((ak4[l]>>2)&1);
    }
    int br[2], bn4[2], bbase[2];
#pragma unroll
    for (int l = 0; l < 2; l++) {
        int idx = tid + l*256;
        br[l]  = idx >> 4;
        bn4[l] = (idx & 15) << 2;
        bbase[l] = (((br[l]>>3)*8 + (bn4[l]>>3))*32
                    + ((bn4[l]&7)<<2) + (br[l]&3))*2 + ((br[l]>>2)&1);
    }

    float4 pa[2], pb[2];
    // load P~, rescale to final attn, write back, keep scaled value for mma
    auto load_tiles = [&](int k0) {
        int tile = k0 >> 7;
#pragma unroll
        for (int l = 0; l < 2; l++) {
            float* ap = &attn[((size_t)(bh*CLQ + q0 + am[l]))*CLKV + k0 + ak4[l]];
            float4 v = *(const float4*)ap;
            float f = frow[((size_t)(bh*CLQ + q0 + am[l]))*NTILE + tile];
            v.x *= f; v.y *= f; v.z *= f; v.w *= f;
            *(float4*)ap = v;
            pa[l] = v;
        }
#pragma unroll
        for (int l = 0; l < 2; l++)
            pb[l] = *(const float4*)&vp[((size_t)(b*CLKV + k0 + br[l]))*CDIM + h*CHEAD + bn4[l]];
    };
    auto stage = [&](float* Ap, float* Bp) {
#pragma unroll
        for (int l = 0; l < 2; l++) {
            Ap[abase[l] + 0]  = __uint_as_float(f2tf32(pa[l].x));
            Ap[abase[l] + 4]  = __uint_as_float(f2tf32(pa[l].y));
            Ap[abase[l] + 8]  = __uint_as_float(f2tf32(pa[l].z));
            Ap[abase[l] + 12] = __uint_as_float(f2tf32(pa[l].w));
        }
#pragma unroll
        for (int l = 0; l < 2; l++) {
            Bp[bbase[l] + 0]  = __uint_as_float(f2tf32(pb[l].x));
            Bp[bbase[l] + 8]  = __uint_as_float(f2tf32(pb[l].y));
            Bp[bbase[l] + 16] = __uint_as_float(f2tf32(pb[l].z));
            Bp[bbase[l] + 24] = __uint_as_float(f2tf32(pb[l].w));
        }
    };

    float c[4][4] = {};

    load_tiles(kbeg);
    stage(As, Bs);
    if (kbeg + 32 < kend) load_tiles(kbeg + 32);
    __syncthreads();

    for (int k0 = kbeg; k0 < kend; k0 += 32) {
        const int p = ((k0 - kbeg) >> 5) & 1;
        const uint32_t* Asu = (const uint32_t*)(As + p * ASZ);
        const uint32_t* Bsu = (const uint32_t*)(Bs + p * BSZ);
        if (k0 + 32 < kend) {
            stage(As + (p^1)*ASZ, Bs + (p^1)*BSZ);
            if (k0 + 64 < kend) load_tiles(k0 + 64);
        }
#pragma unroll
        for (int k8 = 0; k8 < 4; k8++) {
            uint4 a = *(const uint4*)&Asu[((k8*4 + wr)*32 + lane)*4];
            uint2 bb[4];
#pragma unroll
            for (int j = 0; j < 4; j++)
                bb[j] = *(const uint2*)&Bsu[((k8*8 + wc*4 + j)*32 + lane)*2];
#pragma unroll
            for (int j = 0; j < 4; j++)
                mma_tf32(c[j], a.x, a.y, a.z, a.w, bb[j].x, bb[j].y);
        }
        __syncthreads();
    }
    float* Co = part + (size_t)blockIdx.z * X_ELEMS;
#pragma unroll
    for (int j = 0; j < 4; j++) {
        int row = q0 + wr*16 + (lane >> 2);
        int col = h*CHEAD + wc*32 + j*8 + ((lane & 3) << 1);
        *(float2*)&Co[((size_t)(b*CLQ + row))*CDIM + col] =
            make_float2(c[j][0], c[j][1]);
        *(float2*)&Co[((size_t)(b*CLQ + row + 8))*CDIM + col] =
            make_float2(c[j][2], c[j][3]);
    }
}

// ---------------- launch ----------------------------------------------------
extern "C" void kernel_launch(void* const* d_in, const int* in_sizes, int n_in,
                              void* d_out, int out_size)
{
    const float* q    = (const float*)d_in[0];
    const float* kv   = (const float*)d_in[1];
    const float* q_gw = (const float*)d_in[2];
    const float* q_gb = (const float*)d_in[3];
    const float* q_w  = (const float*)d_in[4];
    const float* q_b  = (const float*)d_in[5];
    const float* k_gw = (const float*)d_in[6];
    const float* k_gb = (const float*)d_in[7];
    const float* k_w  = (const float*)d_in[8];
    const float* k_b  = (const float*)d_in[9];
    const float* v_gw = (const float*)d_in[10];
    const float* v_gb = (const float*)d_in[11];
    const float* v_w  = (const float*)d_in[12];
    const float* v_b  = (const float*)d_in[13];
    const float* o_gw = (const float*)d_in[14];
    const float* o_gb = (const float*)d_in[15];
    const float* o_w  = (const float*)d_in[16];
    const float* o_b  = (const float*)d_in[17];
    float* out = (float*)d_out;

    static float *qp=nullptr,*kp=nullptr,*vp=nullptr,*xbuf=nullptr;
    static float *gq=nullptr,*gk=nullptr,*gv=nullptr,*go=nullptr,*afb=nullptr;
    static float *gbk=nullptr,*gbv=nullptr,*part=nullptr;
    static float *mrow=nullptr,*srow=nullptr,*frow=nullptr;
    static cudaStream_t s1, s2;
    static cudaEvent_t ev0, evA, evC;
    if (!qp) {
        cudaGetSymbolAddress((void**)&qp,   g_qp);
        cudaGetSymbolAddress((void**)&kp,   g_kp);
        cudaGetSymbolAddress((void**)&vp,   g_vp);
        cudaGetSymbolAddress((void**)&xbuf, g_xbuf);
        cudaGetSymbolAddress((void**)&gq,   g_gq);
        cudaGetSymbolAddress((void**)&gk,   g_gk);
        cudaGetSymbolAddress((void**)&gv,   g_gv);
        cudaGetSymbolAddress((void**)&go,   g_go);
        cudaGetSymbolAddress((void**)&afb,  g_attn_fb);
        cudaGetSymbolAddress((void**)&gbk,  g_gbk);
        cudaGetSymbolAddress((void**)&gbv,  g_gbv);
        cudaGetSymbolAddress((void**)&part, g_part);
        cudaGetSymbolAddress((void**)&mrow, g_mrow);
        cudaGetSymbolAddress((void**)&srow, g_srow);
        cudaGetSymbolAddress((void**)&frow, g_frow);
        cudaStreamCreateWithFlags(&s1, cudaStreamNonBlocking);
        cudaStreamCreateWithFlags(&s2, cudaStreamNonBlocking);
        cudaEventCreateWithFlags(&ev0, cudaEventDisableTiming);
        cudaEventCreateWithFlags(&evA, cudaEventDisableTiming);
        cudaEventCreateWithFlags(&evC, cudaEventDisableTiming);
    }
    // output layout: x (524288 floats) then attn (33554432 floats)
    float* attn = (out_size >= (X_ELEMS + ATTN_ELEMS)) ? (out + X_ELEMS) : afb;

    // fork
    cudaEventRecord(ev0, 0);
    cudaStreamWaitEvent(s1, ev0, 0);
    cudaStreamWaitEvent(s2, ev0, 0);

    // s1: Q-projection chain
    gate_kernel<<<CTQ/8, 256, 0, s1>>>(q, q_gw, q_gb, gq, CTQ);
    moe_mma<64,64,2,2,32><<<dim3(CDIM/64, CTQ/64, KSPLIT), 128, 0, s1>>>(q, gq, q_w, nullptr, part, CK/KSPLIT, CTQ);
    reduce_kg<<<CTQ/8, 256, 0, s1>>>(part, gq, q_b, qp);
    cudaEventRecord(evA, s1);

    // s2: V-projection chain
    gate_kernel<<<CTKV/8, 256, 0, s2>>>(kv, v_gw, v_gb, gv, CTKV);
    gbias_kernel<<<CTKV/16, 256, 0, s2>>>(gv, v_b, gbv);
    moe_mma<128,64,4,2,32><<<dim3(CDIM/64, CTKV/128, 1), 256, 0, s2>>>(kv, gv, v_w, gbv, vp, CK, CTKV);
    cudaEventRecord(evC, s2);

    // main stream: K-projection chain
    gate_kernel<<<CTKV/8, 256>>>(kv, k_gw, k_gb, gk, CTKV);
    gbias_kernel<<<CTKV/16, 256>>>(gk, k_b, gbk);
    moe_mma<128,64,4,2,32><<<dim3(CDIM/64, CTKV/128, 1), 256>>>(kv, gk, k_w, gbk, kp, CK, CTKV);

    // attention
    cudaStreamWaitEvent((cudaStream_t)0, evA, 0);
    qk_mma<<<dim3(CLKV/128, CLQ/64, CB*CH), 256>>>(qp, kp, attn, mrow, srow);
    sm_combine<<<NROWS/8, 256>>>(mrow, srow, frow);
    cudaStreamWaitEvent((cudaStream_t)0, evC, 0);
    av_mma<<<dim3(CLQ/64, CB*CH, AVSPLIT), 256>>>(attn, vp, frow, part);
    reduce_av<<<X_ELEMS/1024, 256>>>(part, xbuf);

    // output projection
    gate_kernel<<<CTQ/8, 256>>>(xbuf, o_gw, o_gb, go, CTQ);
    moe_mma<64,64,2,2,32><<<dim3(CDIM/64, CTQ/64, KSPLIT), 128>>>(xbuf, go, o_w, nullptr, part, CK/KSPLIT, CTQ);
    reduce_kg<<<CTQ/8, 256>>>(part, go, o_b, out);
}

// round 13
// speedup vs baseline: 1.9469x; 1.0210x over previous
#include <cuda_runtime.h>
#include <math.h>
#include <stdint.h>

#define CB 2
#define CLQ 512
#define CLKV 4096
#define CDIM 512
#define CH 8
#define CE 10
#define CTOPK 5
#define CHEAD 64
#define CTQ (CB*CLQ)      /* 1024 */
#define CTKV (CB*CLKV)    /* 8192 */
#define CK (CE*CDIM)      /* 5120 */
#define CSCALE 0.125f
#define X_ELEMS (CTQ*CDIM)              /* 524288 */
#define ATTN_ELEMS (CB*CH*CLQ*CLKV)     /* 33554432 */
#define KSPLIT 8
#define AVSPLIT 8
#define NROWS (CB*CH*CLQ)               /* 8192 attn rows */
#define NTILE (CLKV/128)                /* 32 k-tiles per row */

// ---------------- scratch (static device globals) ---------------------------
__device__ float g_qp[CTQ*CDIM];
__device__ float g_kp[CTKV*CDIM];
__device__ float g_vp[CTKV*CDIM];
__device__ float g_xbuf[CTQ*CDIM];
__device__ float g_gq[CTQ*CE];
__device__ float g_gk[CTKV*CE];
__device__ float g_gv[CTKV*CE];
__device__ float g_go[CTQ*CE];
__device__ float g_gbk[CTKV*CDIM];
__device__ float g_gbv[CTKV*CDIM];
__device__ float g_part[KSPLIT*CTQ*CDIM];
__device__ float g_mrow[NROWS*NTILE];
__device__ float g_srow[NROWS*NTILE];
__device__ float g_frow[NROWS*NTILE];
__device__ float g_attn_fb[ATTN_ELEMS];

// ---------------- helpers ---------------------------------------------------
__device__ __forceinline__ uint32_t f2tf32(float x) {
    uint32_t u;
    asm("cvt.rna.tf32.f32 %0, %1;" : "=r"(u) : "f"(x));
    return u;
}

__device__ __forceinline__ void mma_tf32(float c[4],
                                         uint32_t a0, uint32_t a1, uint32_t a2, uint32_t a3,
                                         uint32_t b0, uint32_t b1) {
    asm volatile(
        "mma.sync.aligned.m16n8k8.row.col.f32.tf32.tf32.f32 "
        "{%0,%1,%2,%3}, {%4,%5,%6,%7}, {%8,%9}, {%0,%1,%2,%3};"
        : "+f"(c[0]), "+f"(c[1]), "+f"(c[2]), "+f"(c[3])
        : "r"(a0), "r"(a1), "r"(a2), "r"(a3), "r"(b0), "r"(b1));
}

// ---------------- gate: softmax -> top-5 -> renormalize (warp/token) --------
__global__ void gate_kernel(const float* __restrict__ x,
                            const float* __restrict__ gw,   // [512, E]
                            const float* __restrict__ gb,   // [E]
                            float* __restrict__ g,          // [T, E]
                            int T)
{
    int tok  = (blockIdx.x * blockDim.x + threadIdx.x) >> 5;
    int lane = threadIdx.x & 31;
    if (tok >= T) return;
    const float* xr = x + (size_t)tok * CDIM;
    float acc[CE];
#pragma unroll
    for (int e = 0; e < CE; e++) acc[e] = 0.f;
    for (int i = lane; i < CDIM; i += 32) {
        float xv = xr[i];
        const float* gr = gw + (size_t)i * CE;
#pragma unroll
        for (int e = 0; e < CE; e++) acc[e] += xv * gr[e];
    }
#pragma unroll
    for (int e = 0; e < CE; e++) {
#pragma unroll
        for (int o = 16; o > 0; o >>= 1)
            acc[e] += __shfl_xor_sync(0xffffffffu, acc[e], o);
    }
    if (lane == 0) {
        float l[CE];
#pragma unroll
        for (int e = 0; e < CE; e++) l[e] = acc[e] + gb[e];
        bool used[CE];
#pragma unroll
        for (int e = 0; e < CE; e++) used[e] = false;
        int sel[CTOPK];
        float m = -3.4e38f;
        for (int k = 0; k < CTOPK; k++) {          // strict >: first index wins ties
            int best = 0; float bv = -3.4e38f;
            for (int e = 0; e < CE; e++)
                if (!used[e] && l[e] > bv) { bv = l[e]; best = e; }
            used[best] = true; sel[k] = best;
            if (k == 0) m = bv;
        }
        float ex[CTOPK]; float s = 0.f;
        for (int k = 0; k < CTOPK; k++) { ex[k] = __expf(l[sel[k]] - m); s += ex[k]; }
        float inv = 1.f / s;
        float outv[CE];
#pragma unroll
        for (int e = 0; e < CE; e++) outv[e] = 0.f;
        for (int k = 0; k < CTOPK; k++) outv[sel[k]] = ex[k] * inv;
        float* gr = g + (size_t)tok * CE;
        for (int e = 0; e < CE; e++) gr[e] = outv[e];
    }
}

// ---------------- gbias = g @ bias, bias cached in smem (16 tokens/block) ---
__global__ void __launch_bounds__(256) gbias_kernel(const float* __restrict__ G,
                                                    const float* __restrict__ bias,  // [E,512]
                                                    float* __restrict__ gbias)       // [T,512]
{
    __shared__ float bs[CE*CDIM];    // 20KB
    __shared__ float gs[16*CE];
    int tid = threadIdx.x;
    for (int i = tid; i < CE*CDIM; i += 256) bs[i] = bias[i];
    for (int i = tid; i < 16*CE; i += 256) gs[i] = G[(size_t)blockIdx.x*16*CE + i];
    __syncthreads();
    int lane = tid & 31;
    int wrow = tid >> 5;    // 0..7
#pragma unroll
    for (int tt = 0; tt < 2; tt++) {
        int tr = tt*8 + wrow;
        size_t row = (size_t)blockIdx.x*16 + tr;
        float ge[CE];
#pragma unroll
        for (int e = 0; e < CE; e++) ge[e] = gs[tr*CE + e];
#pragma unroll
        for (int v = 0; v < 4; v++) {
            int c = lane*4 + v*128;
            float4 s = make_float4(0.f,0.f,0.f,0.f);
#pragma unroll
            for (int e = 0; e < CE; e++) {
                float4 b4 = *(const float4*)&bs[e*CDIM + c];
                s.x += ge[e]*b4.x; s.y += ge[e]*b4.y;
                s.z += ge[e]*b4.z; s.w += ge[e]*b4.w;
            }
            *(float4*)&gbias[row*CDIM + c] = s;
        }
    }
}

// --------- tf32 tensor-core MoE GEMM, BK=32, double-buffered, split-K -------
template<int BM, int BN, int WR, int WC, int BK>
__global__ void __launch_bounds__(WR*WC*32) moe_mma(const float* __restrict__ X,
                                                    const float* __restrict__ G,
                                                    const float* __restrict__ W,
                                                    const float* __restrict__ GB,
                                                    float* __restrict__ C,
                                                    int klen, int m_rows)
{
    constexpr int THREADS = WR * WC * 32;
    constexpr int MT = BM / WR / 16;
    constexpr int NT = BN / WC / 8;
    constexpr int KF4 = BK / 4;
    constexpr int KC  = BK / 8;
    constexpr int LA = BM * KF4 / THREADS;
    constexpr int LB = BK * (BN/4) / THREADS;
    constexpr int ASZ = KC * (BM/16) * 32 * 4;
    constexpr int BSZ = KC * (BN/8)  * 32 * 2;

    __shared__ float As[2 * ASZ];
    __shared__ float Bs[2 * BSZ];

    const int tid  = threadIdx.x;
    const int w    = tid >> 5;
    const int lane = tid & 31;
    const int wr   = w / WC;
    const int wc   = w % WC;
    const int bm   = blockIdx.y * BM;
    const int bn   = blockIdx.x * BN;
    const int kbeg = blockIdx.z * klen;
    const int kend = kbeg + klen;

    int am[LA], akk[LA], abase[LA];
#pragma unroll
    for (int l = 0; l < LA; l++) {
        int idx = tid + l * THREADS;
        am[l]  = idx / KF4;
        akk[l] = (idx % KF4) << 2;
        int k8 = akk[l] >> 3;
        int mt = am[l] >> 4;
        abase[l] = ((k8 * (BM/16) + mt) * 32 + ((am[l] & 7) << 2)) * 4
                 + ((am[l] >> 3) & 1) + 2 * ((akk[l] >> 2) & 1);
    }
    int br[LB], bn4[LB], bbase[LB];
#pragma unroll
    for (int l = 0; l < LB; l++) {
        int idx = tid + l * THREADS;
        br[l]  = idx / (BN/4);
        bn4[l] = (idx % (BN/4)) << 2;
        bbase[l] = (((br[l] >> 3) * (BN/8) + (bn4[l] >> 3)) * 32
                    + ((bn4[l] & 7) << 2) + (br[l] & 3)) * 2 + ((br[l] >> 2) & 1);
    }

    float4 pa[LA], pb[LB];
    float  ga[LA];
    auto load_tiles = [&](int k0) {
#pragma unroll
        for (int l = 0; l < LA; l++) {
            pa[l] = *(const float4*)&X[(size_t)(bm + am[l]) * CDIM + (k0 & 511) + akk[l]];
            ga[l] = G[(size_t)(bm + am[l]) * CE + (k0 >> 9)];
        }
#pragma unroll
        for (int l = 0; l < LB; l++)
            pb[l] = *(const float4*)&W[(size_t)(k0 + br[l]) * CDIM + bn + bn4[l]];
    };
    auto stage = [&](float* Ap, float* Bp) {
#pragma unroll
        for (int l = 0; l < LA; l++) {
            float g = ga[l];
            Ap[abase[l] + 0]  = __uint_as_float(f2tf32(pa[l].x * g));
            Ap[abase[l] + 4]  = __uint_as_float(f2tf32(pa[l].y * g));
            Ap[abase[l] + 8]  = __uint_as_float(f2tf32(pa[l].z * g));
            Ap[abase[l] + 12] = __uint_as_float(f2tf32(pa[l].w * g));
        }
#pragma unroll
        for (int l = 0; l < LB; l++) {
            Bp[bbase[l] + 0]  = __uint_as_float(f2tf32(pb[l].x));
            Bp[bbase[l] + 8]  = __uint_as_float(f2tf32(pb[l].y));
            Bp[bbase[l] + 16] = __uint_as_float(f2tf32(pb[l].z));
            Bp[bbase[l] + 24] = __uint_as_float(f2tf32(pb[l].w));
        }
    };

    float c[MT][NT][4] = {};

    load_tiles(kbeg);
    stage(As, Bs);
    if (kbeg + BK < kend) load_tiles(kbeg + BK);
    __syncthreads();

    for (int k0 = kbeg; k0 < kend; k0 += BK) {
        const int p = ((k0 - kbeg) / BK) & 1;
        const uint32_t* Asu = (const uint32_t*)(As + p * ASZ);
        const uint32_t* Bsu = (const uint32_t*)(Bs + p * BSZ);
        if (k0 + BK < kend) {
            stage(As + (p^1) * ASZ, Bs + (p^1) * BSZ);
            if (k0 + 2*BK < kend) load_tiles(k0 + 2*BK);
        }
#pragma unroll
        for (int k8 = 0; k8 < KC; k8++) {
            uint4 a[MT];
            uint2 b[NT];
#pragma unroll
            for (int i = 0; i < MT; i++)
                a[i] = *(const uint4*)&Asu[((k8 * (BM/16) + wr*MT + i) * 32 + lane) * 4];
#pragma unroll
            for (int j = 0; j < NT; j++)
                b[j] = *(const uint2*)&Bsu[((k8 * (BN/8) + wc*NT + j) * 32 + lane) * 2];
#pragma unroll
            for (int i = 0; i < MT; i++)
#pragma unroll
                for (int j = 0; j < NT; j++)
                    mma_tf32(c[i][j], a[i].x, a[i].y, a[i].z, a[i].w, b[j].x, b[j].y);
        }
        __syncthreads();
    }

    const bool split = (gridDim.z > 1);
    float* Co = C + (split ? (size_t)blockIdx.z * m_rows * CDIM : 0);
#pragma unroll
    for (int i = 0; i < MT; i++) {
#pragma unroll
        for (int j = 0; j < NT; j++) {
            int row = bm + wr*MT*16 + i*16 + (lane >> 2);
            int col = bn + wc*NT*8 + j*8 + ((lane & 3) << 1);
            float b00 = 0.f, b01 = 0.f, b10 = 0.f, b11 = 0.f;
            if (!split) {
                float2 b0 = *(const float2*)&GB[(size_t)row * CDIM + col];
                float2 b1 = *(const float2*)&GB[(size_t)(row + 8) * CDIM + col];
                b00 = b0.x; b01 = b0.y; b10 = b1.x; b11 = b1.y;
            }
            *(float2*)&Co[(size_t)row * CDIM + col] =
                make_float2(c[i][j][0] + b00, c[i][j][1] + b01);
            *(float2*)&Co[(size_t)(row + 8) * CDIM + col] =
                make_float2(c[i][j][2] + b10, c[i][j][3] + b11);
        }
    }
}

// ------- split-K reduce with gate-bias fold: out = Σ part + Σ_e g·bias ------
__global__ void __launch_bounds__(256) reduce_kg(const float* __restrict__ part,
                                                 const float* __restrict__ G,
                                                 const float* __restrict__ bias,  // [E,512]
                                                 float* __restrict__ out)
{
    __shared__ float bs[CE*CDIM];    // 20KB
    int tid = threadIdx.x;
    for (int i = tid; i < CE*CDIM; i += 256) bs[i] = bias[i];
    __syncthreads();
    int lane = tid & 31;
    size_t row = (size_t)blockIdx.x*8 + (tid >> 5);
    float ge[CE];
#pragma unroll
    for (int e = 0; e < CE; e++) ge[e] = G[row*CE + e];
#pragma unroll
    for (int v = 0; v < 4; v++) {
        int c = lane*4 + v*128;
        size_t i = row*CDIM + c;
        float4 s = make_float4(0.f,0.f,0.f,0.f);
#pragma unroll
        for (int z = 0; z < KSPLIT; z++) {
            float4 p = *(const float4*)&part[(size_t)z * X_ELEMS + i];
            s.x += p.x; s.y += p.y; s.z += p.z; s.w += p.w;
        }
#pragma unroll
        for (int e = 0; e < CE; e++) {
            float4 b4 = *(const float4*)&bs[e*CDIM + c];
            s.x += ge[e]*b4.x; s.y += ge[e]*b4.y;
            s.z += ge[e]*b4.z; s.w += ge[e]*b4.w;
        }
        *(float4*)&out[i] = s;
    }
}

__global__ void __launch_bounds__(256) reduce_av(const float* __restrict__ part,
                                                 float* __restrict__ out)
{
    int i = (blockIdx.x * 256 + threadIdx.x) << 2;
    float4 s = *(const float4*)&part[i];
#pragma unroll
    for (int z = 1; z < AVSPLIT; z++) {
        float4 p = *(const float4*)&part[(size_t)z * X_ELEMS + i];
        s.x += p.x; s.y += p.y; s.z += p.z; s.w += p.w;
    }
    *(float4*)&out[i] = s;
}

// ---- QK^T*scale + tile softmax stats; writes P~=exp(l - m_tile) to attn ----
__global__ void __launch_bounds__(256) qk_mma(const float* __restrict__ qp,
                                              const float* __restrict__ kp,
                                              float* __restrict__ attn,
                                              float* __restrict__ mrow,
                                              float* __restrict__ srow)
{
    __shared__ float As[8 * 4  * 32 * 4];
    __shared__ float Bs[8 * 16 * 32 * 2];
    __shared__ float sred[4*64];
    const int bh = blockIdx.z;
    const int b = bh >> 3, h = bh & 7;
    const int q0 = blockIdx.y << 6;
    const int k0 = blockIdx.x << 7;
    const int tid = threadIdx.x;
    const int w = tid >> 5, lane = tid & 31;
    const int wr = w >> 2, wc = w & 3;      // 2 x 4 warps, MT=2, NT=4

#pragma unroll
    for (int l = 0; l < 4; l++) {
        int idx = tid + l*256;
        int am = idx >> 4;
        int ak4 = (idx & 15) << 2;
        float4 v = *(const float4*)&qp[((size_t)(b*CLQ + q0 + am))*CDIM + h*CHEAD + ak4];
        int k8 = ak4 >> 3;
        int base = ((k8*4 + (am>>4))*32 + ((am&7)<<2))*4 + ((am>>3)&1) + 2*((ak4>>2)&1);
        As[base + 0]  = __uint_as_float(f2tf32(v.x * CSCALE));
        As[base + 4]  = __uint_as_float(f2tf32(v.y * CSCALE));
        As[base + 8]  = __uint_as_float(f2tf32(v.z * CSCALE));
        As[base + 12] = __uint_as_float(f2tf32(v.w * CSCALE));
    }
#pragma unroll
    for (int l = 0; l < 8; l++) {
        int idx = tid + l*256;
        int n = idx >> 4;
        int bk4 = (idx & 15) << 2;
        float4 v = *(const float4*)&kp[((size_t)(b*CLKV + k0 + n))*CDIM + h*CHEAD + bk4];
        int k8 = bk4 >> 3;
        int base = ((k8*16 + (n>>3))*32 + ((n&7)<<2))*2 + ((bk4>>2)&1);
        Bs[base + 0] = __uint_as_float(f2tf32(v.x));
        Bs[base + 2] = __uint_as_float(f2tf32(v.y));
        Bs[base + 4] = __uint_as_float(f2tf32(v.z));
        Bs[base + 6] = __uint_as_float(f2tf32(v.w));
    }
    __syncthreads();

    const uint32_t* Asu = (const uint32_t*)As;
    const uint32_t* Bsu = (const uint32_t*)Bs;
    float c[2][4][4] = {};
#pragma unroll
    for (int k8 = 0; k8 < 8; k8++) {
        uint4 a[2];
        uint2 bb[4];
#pragma unroll
        for (int i = 0; i < 2; i++)
            a[i] = *(const uint4*)&Asu[((k8*4 + wr*2 + i)*32 + lane)*4];
#pragma unroll
        for (int j = 0; j < 4; j++)
            bb[j] = *(const uint2*)&Bsu[((k8*16 + wc*4 + j)*32 + lane)*2];
#pragma unroll
        for (int i = 0; i < 2; i++)
#pragma unroll
            for (int j = 0; j < 4; j++)
                mma_tf32(c[i][j], a[i].x, a[i].y, a[i].z, a[i].w, bb[j].x, bb[j].y);
    }

    // --- per-row tile max across the 128-k tile ---
    float tmax[2][2];
#pragma unroll
    for (int i = 0; i < 2; i++)
#pragma unroll
        for (int hh = 0; hh < 2; hh++) {
            float m = -3.4e38f;
#pragma unroll
            for (int j = 0; j < 4; j++) {
                m = fmaxf(m, c[i][j][2*hh+0]);
                m = fmaxf(m, c[i][j][2*hh+1]);
            }
#pragma unroll
            for (int o = 1; o <= 2; o <<= 1)
                m = fmaxf(m, __shfl_xor_sync(~0u, m, o));
            tmax[i][hh] = m;
        }
    if ((lane & 3) == 0) {
#pragma unroll
        for (int i = 0; i < 2; i++)
#pragma unroll
            for (int hh = 0; hh < 2; hh++) {
                int lr = wr*32 + i*16 + hh*8 + (lane >> 2);
                sred[wc*64 + lr] = tmax[i][hh];
            }
    }
    __syncthreads();
    float rmax[2][2];
#pragma unroll
    for (int i = 0; i < 2; i++)
#pragma unroll
        for (int hh = 0; hh < 2; hh++) {
            int lr = wr*32 + i*16 + hh*8 + (lane >> 2);
            float m = fmaxf(fmaxf(sred[lr], sred[64+lr]),
                            fmaxf(sred[128+lr], sred[192+lr]));
            rmax[i][hh] = m;
        }
    __syncthreads();
    // --- exponentiate in place + per-row tile sum ---
    float tsum[2][2] = {};
#pragma unroll
    for (int i = 0; i < 2; i++)
#pragma unroll
        for (int j = 0; j < 4; j++)
#pragma unroll
            for (int hh = 0; hh < 2; hh++) {
                float e0 = __expf(c[i][j][2*hh+0] - rmax[i][hh]);
                float e1 = __expf(c[i][j][2*hh+1] - rmax[i][hh]);
                c[i][j][2*hh+0] = e0;
                c[i][j][2*hh+1] = e1;
                tsum[i][hh] += e0 + e1;
            }
#pragma unroll
    for (int i = 0; i < 2; i++)
#pragma unroll
        for (int hh = 0; hh < 2; hh++)
#pragma unroll
            for (int o = 1; o <= 2; o <<= 1)
                tsum[i][hh] += __shfl_xor_sync(~0u, tsum[i][hh], o);
    if ((lane & 3) == 0) {
#pragma unroll
        for (int i = 0; i < 2; i++)
#pragma unroll
            for (int hh = 0; hh < 2; hh++) {
                int lr = wr*32 + i*16 + hh*8 + (lane >> 2);
                sred[wc*64 + lr] = tsum[i][hh];
            }
    }
    __syncthreads();
    if (wc == 0 && (lane & 3) == 0) {
#pragma unroll
        for (int i = 0; i < 2; i++)
#pragma unroll
            for (int hh = 0; hh < 2; hh++) {
                int lr = wr*32 + i*16 + hh*8 + (lane >> 2);
                float s = sred[lr] + sred[64+lr] + sred[128+lr] + sred[192+lr];
                size_t ridx = ((size_t)bh*CLQ + q0 + lr)*NTILE + blockIdx.x;
                mrow[ridx] = rmax[i][hh];
                srow[ridx] = s;
            }
    }

    // --- store P~ ---
#pragma unroll
    for (int i = 0; i < 2; i++) {
#pragma unroll
        for (int j = 0; j < 4; j++) {
            int row = q0 + wr*32 + i*16 + (lane >> 2);
            int col = k0 + wc*32 + j*8 + ((lane & 3) << 1);
            *(float2*)&attn[((size_t)(bh*CLQ + row))*CLKV + col] =
                make_float2(c[i][j][0], c[i][j][1]);
            *(float2*)&attn[((size_t)(bh*CLQ + row + 8))*CLKV + col] =
                make_float2(c[i][j][2], c[i][j][3]);
        }
    }
}

// ---- combine tile stats -> per-(row,tile) rescale factor f = exp(m_t-m)/S --
__global__ void __launch_bounds__(256) sm_combine(const float* __restrict__ mrow,
                                                  const float* __restrict__ srow,
                                                  float* __restrict__ frow)
{
    size_t row = (size_t)blockIdx.x*8 + (threadIdx.x >> 5);
    int t = threadIdx.x & 31;
    float m = mrow[row*NTILE + t];
    float s = srow[row*NTILE + t];
    float gm = m;
#pragma unroll
    for (int o = 16; o > 0; o >>= 1) gm = fmaxf(gm, __shfl_xor_sync(~0u, gm, o));
    float e = __expf(m - gm);
    float ws = s * e;
#pragma unroll
    for (int o = 16; o > 0; o >>= 1) ws += __shfl_xor_sync(~0u, ws, o);
    frow[row*NTILE + t] = e / ws;
}

// ---- P @ V: rescale P~ -> final attn (written back) + mma, split-K over KV -
__global__ void __launch_bounds__(256) av_mma(float* __restrict__ attn,
                                              const float* __restrict__ vp,
                                              const float* __restrict__ frow,
                                              float* __restrict__ part)
{
    constexpr int ASZ = 4 * 4 * 32 * 4;
    constexpr int BSZ = 4 * 8 * 32 * 2;
    __shared__ float As[2 * ASZ];
    __shared__ float Bs[2 * BSZ];
    const int bh = blockIdx.y;
    const int b = bh >> 3, h = bh & 7;
    const int q0 = blockIdx.x << 6;
    const int kbeg = blockIdx.z * (CLKV / AVSPLIT);
    const int kend = kbeg + (CLKV / AVSPLIT);
    const int tid = threadIdx.x;
    const int w = tid >> 5, lane = tid & 31;
    const int wr = w >> 1, wc = w & 1;     // 4 x 2 warps, MT=1, NT=4

    int am[2], ak4[2], abase[2];
#pragma unroll
    for (int l = 0; l < 2; l++) {
        int idx = tid + l*256;
        am[l]  = idx >> 3;
        ak4[l] = (idx & 7) << 2;
        int k8 = ak4[l] >> 3;
        abase[l] = ((k8*4 + (am[l]>>4))*32 + ((am[l]&7)<<2))*4
                 + ((am[l]>>3)&1) + 2*((ak4[l]>>2)&1);
    }
    int br[2], bn4[2], bbase[2];
#pragma unroll
    for (int l = 0; l < 2; l++) {
        int idx = tid + l*256;
        br[l]  = idx >> 4;
        bn4[l] = (idx & 15) << 2;
        bbase[l] = (((br[l]>>3)*8 + (bn4[l]>>3))*32
                    + ((bn4[l]&7)<<2) + (br[l]&3))*2 + ((br[l]>>2)&1);
    }

    float4 pa[2], pb[2];
    // load P~, rescale to final attn, write back, keep scaled value for mma
    auto load_tiles = [&](int k0) {
        int tile = k0 >> 7;
#pragma unroll
        for (int l = 0; l < 2; l++) {
            float* ap = &attn[((size_t)(bh*CLQ + q0 + am[l]))*CLKV + k0 + ak4[l]];
            float4 v = *(const float4*)ap;
            float f = frow[((size_t)(bh*CLQ + q0 + am[l]))*NTILE + tile];
            v.x *= f; v.y *= f; v.z *= f; v.w *= f;
            *(float4*)ap = v;
            pa[l] = v;
        }
#pragma unroll
        for (int l = 0; l < 2; l++)
            pb[l] = *(const float4*)&vp[((size_t)(b*CLKV + k0 + br[l]))*CDIM + h*CHEAD + bn4[l]];
    };
    auto stage = [&](float* Ap, float* Bp) {
#pragma unroll
        for (int l = 0; l < 2; l++) {
            Ap[abase[l] + 0]  = __uint_as_float(f2tf32(pa[l].x));
            Ap[abase[l] + 4]  = __uint_as_float(f2tf32(pa[l].y));
            Ap[abase[l] + 8]  = __uint_as_float(f2tf32(pa[l].z));
            Ap[abase[l] + 12] = __uint_as_float(f2tf32(pa[l].w));
        }
#pragma unroll
        for (int l = 0; l < 2; l++) {
            Bp[bbase[l] + 0]  = __uint_as_float(f2tf32(pb[l].x));
            Bp[bbase[l] + 8]  = __uint_as_float(f2tf32(pb[l].y));
            Bp[bbase[l] + 16] = __uint_as_float(f2tf32(pb[l].z));
            Bp[bbase[l] + 24] = __uint_as_float(f2tf32(pb[l].w));
        }
    };

    float c[4][4] = {};

    load_tiles(kbeg);
    stage(As, Bs);
    if (kbeg + 32 < kend) load_tiles(kbeg + 32);
    __syncthreads();

    for (int k0 = kbeg; k0 < kend; k0 += 32) {
        const int p = ((k0 - kbeg) >> 5) & 1;
        const uint32_t* Asu = (const uint32_t*)(As + p * ASZ);
        const uint32_t* Bsu = (const uint32_t*)(Bs + p * BSZ);
        if (k0 + 32 < kend) {
            stage(As + (p^1)*ASZ, Bs + (p^1)*BSZ);
            if (k0 + 64 < kend) load_tiles(k0 + 64);
        }
#pragma unroll
        for (int k8 = 0; k8 < 4; k8++) {
            uint4 a = *(const uint4*)&Asu[((k8*4 + wr)*32 + lane)*4];
            uint2 bb[4];
#pragma unroll
            for (int j = 0; j < 4; j++)
                bb[j] = *(const uint2*)&Bsu[((k8*8 + wc*4 + j)*32 + lane)*2];
#pragma unroll
            for (int j = 0; j < 4; j++)
                mma_tf32(c[j], a.x, a.y, a.z, a.w, bb[j].x, bb[j].y);
        }
        __syncthreads();
    }
    float* Co = part + (size_t)blockIdx.z * X_ELEMS;
#pragma unroll
    for (int j = 0; j < 4; j++) {
        int row = q0 + wr*16 + (lane >> 2);
        int col = h*CHEAD + wc*32 + j*8 + ((lane & 3) << 1);
        *(float2*)&Co[((size_t)(b*CLQ + row))*CDIM + col] =
            make_float2(c[j][0], c[j][1]);
        *(float2*)&Co[((size_t)(b*CLQ + row + 8))*CDIM + col] =
            make_float2(c[j][2], c[j][3]);
    }
}

// ---------------- launch ----------------------------------------------------
extern "C" void kernel_launch(void* const* d_in, const int* in_sizes, int n_in,
                              void* d_out, int out_size)
{
    const float* q    = (const float*)d_in[0];
    const float* kv   = (const float*)d_in[1];
    const float* q_gw = (const float*)d_in[2];
    const float* q_gb = (const float*)d_in[3];
    const float* q_w  = (const float*)d_in[4];
    const float* q_b  = (const float*)d_in[5];
    const float* k_gw = (const float*)d_in[6];
    const float* k_gb = (const float*)d_in[7];
    const float* k_w  = (const float*)d_in[8];
    const float* k_b  = (const float*)d_in[9];
    const float* v_gw = (const float*)d_in[10];
    const float* v_gb = (const float*)d_in[11];
    const float* v_w  = (const float*)d_in[12];
    const float* v_b  = (const float*)d_in[13];
    const float* o_gw = (const float*)d_in[14];
    const float* o_gb = (const float*)d_in[15];
    const float* o_w  = (const float*)d_in[16];
    const float* o_b  = (const float*)d_in[17];
    float* out = (float*)d_out;

    static float *qp=nullptr,*kp=nullptr,*vp=nullptr,*xbuf=nullptr;
    static float *gq=nullptr,*gk=nullptr,*gv=nullptr,*go=nullptr,*afb=nullptr;
    static float *gbk=nullptr,*gbv=nullptr,*part=nullptr;
    static float *mrow=nullptr,*srow=nullptr,*frow=nullptr;
    static cudaStream_t s1, s2;
    static cudaEvent_t ev0, evA, evC;
    if (!qp) {
        cudaGetSymbolAddress((void**)&qp,   g_qp);
        cudaGetSymbolAddress((void**)&kp,   g_kp);
        cudaGetSymbolAddress((void**)&vp,   g_vp);
        cudaGetSymbolAddress((void**)&xbuf, g_xbuf);
        cudaGetSymbolAddress((void**)&gq,   g_gq);
        cudaGetSymbolAddress((void**)&gk,   g_gk);
        cudaGetSymbolAddress((void**)&gv,   g_gv);
        cudaGetSymbolAddress((void**)&go,   g_go);
        cudaGetSymbolAddress((void**)&afb,  g_attn_fb);
        cudaGetSymbolAddress((void**)&gbk,  g_gbk);
        cudaGetSymbolAddress((void**)&gbv,  g_gbv);
        cudaGetSymbolAddress((void**)&part, g_part);
        cudaGetSymbolAddress((void**)&mrow, g_mrow);
        cudaGetSymbolAddress((void**)&srow, g_srow);
        cudaGetSymbolAddress((void**)&frow, g_frow);
        cudaStreamCreateWithFlags(&s1, cudaStreamNonBlocking);
        cudaStreamCreateWithFlags(&s2, cudaStreamNonBlocking);
        cudaEventCreateWithFlags(&ev0, cudaEventDisableTiming);
        cudaEventCreateWithFlags(&evA, cudaEventDisableTiming);
        cudaEventCreateWithFlags(&evC, cudaEventDisableTiming);
    }
    // output layout: x (524288 floats) then attn (33554432 floats)
    float* attn = (out_size >= (X_ELEMS + ATTN_ELEMS)) ? (out + X_ELEMS) : afb;

    // fork
    cudaEventRecord(ev0, 0);
    cudaStreamWaitEvent(s1, ev0, 0);
    cudaStreamWaitEvent(s2, ev0, 0);

    // s1: Q-projection chain
    gate_kernel<<<CTQ/8, 256, 0, s1>>>(q, q_gw, q_gb, gq, CTQ);
    moe_mma<64,64,2,2,32><<<dim3(CDIM/64, CTQ/64, KSPLIT), 128, 0, s1>>>(q, gq, q_w, nullptr, part, CK/KSPLIT, CTQ);
    reduce_kg<<<CTQ/8, 256, 0, s1>>>(part, gq, q_b, qp);
    cudaEventRecord(evA, s1);

    // s2: V-projection chain
    gate_kernel<<<CTKV/8, 256, 0, s2>>>(kv, v_gw, v_gb, gv, CTKV);
    gbias_kernel<<<CTKV/16, 256, 0, s2>>>(gv, v_b, gbv);
    moe_mma<128,64,2,2,32><<<dim3(CDIM/64, CTKV/128, 1), 128, 0, s2>>>(kv, gv, v_w, gbv, vp, CK, CTKV);
    cudaEventRecord(evC, s2);

    // main stream: K-projection chain
    gate_kernel<<<CTKV/8, 256>>>(kv, k_gw, k_gb, gk, CTKV);
    gbias_kernel<<<CTKV/16, 256>>>(gk, k_b, gbk);
    moe_mma<128,64,2,2,32><<<dim3(CDIM/64, CTKV/128, 1), 128>>>(kv, gk, k_w, gbk, kp, CK, CTKV);

    // attention
    cudaStreamWaitEvent((cudaStream_t)0, evA, 0);
    qk_mma<<<dim3(CLKV/128, CLQ/64, CB*CH), 256>>>(qp, kp, attn, mrow, srow);
    sm_combine<<<NROWS/8, 256>>>(mrow, srow, frow);
    cudaStreamWaitEvent((cudaStream_t)0, evC, 0);
    av_mma<<<dim3(CLQ/64, CB*CH, AVSPLIT), 256>>>(attn, vp, frow, part);
    reduce_av<<<X_ELEMS/1024, 256>>>(part, xbuf);

    // output projection
    gate_kernel<<<CTQ/8, 256>>>(xbuf, o_gw, o_gb, go, CTQ);
    moe_mma<64,64,2,2,32><<<dim3(CDIM/64, CTQ/64, KSPLIT), 128>>>(xbuf, go, o_w, nullptr, part, CK/KSPLIT, CTQ);
    reduce_kg<<<CTQ/8, 256>>>(part, go, o_b, out);
}